// round 10
// baseline (speedup 1.0000x reference)
#include <cuda_runtime.h>
#include <cuda_bf16.h>
#include <cuda_fp16.h>
#include <math.h>
#include <stdint.h>

#define NIMG 64          // T*B = 16*4
#define HW   16384       // 128*128
typedef unsigned long long ull;

// Scratch (allocation-free rule: __device__ globals)
__device__ float   g_z [NIMG *  2 * HW];                 //  8 MB integrated input
__device__ float   g_xm[NIMG * 16 * HW];                 // 64 MB head conv output
__device__ float   g_h1[NIMG * 16 * HW];                 // 64 MB sq1 conv output
__device__ uint8_t g_xs[(size_t)NIMG * 128 * 144 * 48];  // 56.6 MB fp16 pixel rows
__device__ uint8_t g_ws[225 * 768];                      // fp16 weights (x1024), 48B rows

#define ROWB 6912                        // 144 px * 48 B
#define A_BYTES (18 * ROWB)              // 124416
#define B_SLICE 11520                    // 15 kx * 768
#define SQ1_SMEM (A_BYTES + 2 * B_SLICE) // 147456 (B double-buffered)

// ---- f32x2 helpers --------------------------------------------------------
__device__ __forceinline__ void fma2(ull& d, ull a, ull b) {
    asm("fma.rn.f32x2 %0, %1, %2, %0;" : "+l"(d) : "l"(a), "l"(b));
}
__device__ __forceinline__ ull pack2(float lo, float hi) {
    ull r; asm("mov.b64 %0, {%1, %2};" : "=l"(r) : "f"(lo), "f"(hi)); return r;
}
__device__ __forceinline__ void unpack2(ull v, float& lo, float& hi) {
    asm("mov.b64 {%0, %1}, %2;" : "=f"(lo), "=f"(hi) : "l"(v));
}

// ---- HMMA helpers ---------------------------------------------------------
__device__ __forceinline__ uint32_t smem_u32(const void* p) {
    uint32_t a;
    asm("{ .reg .u64 t; cvta.to.shared.u64 t, %1; cvt.u32.u64 %0, t; }" : "=r"(a) : "l"(p));
    return a;
}
__device__ __forceinline__ void ldsm4(uint32_t* r, uint32_t a) {
    asm volatile("ldmatrix.sync.aligned.m8n8.x4.shared.b16 {%0,%1,%2,%3}, [%4];"
                 : "=r"(r[0]), "=r"(r[1]), "=r"(r[2]), "=r"(r[3]) : "r"(a));
}
__device__ __forceinline__ void mma_f16(float* d, const uint32_t* a,
                                        uint32_t b0, uint32_t b1) {
    asm volatile(
        "mma.sync.aligned.m16n8k16.row.col.f32.f16.f16.f32 "
        "{%0,%1,%2,%3}, {%4,%5,%6,%7}, {%8,%9}, {%0,%1,%2,%3};"
        : "+f"(d[0]), "+f"(d[1]), "+f"(d[2]), "+f"(d[3])
        : "r"(a[0]), "r"(a[1]), "r"(a[2]), "r"(a[3]), "r"(b0), "r"(b1));
}

// ---------------------------------------------------------------------------
// K1: leaky integration over T per TC slice + mean over TC.
// ---------------------------------------------------------------------------
__global__ void integrate_kernel(const float* __restrict__ x,
                                 const float* __restrict__ mtc_p,
                                 float* __restrict__ z) {
    int idx = blockIdx.x * blockDim.x + threadIdx.x;
    if (idx >= 4 * 2 * HW) return;
    int p  = idx & (HW - 1);
    int bc = idx >> 14;
    int c  = bc & 1;
    int b  = bc >> 1;

    float mtc = *mtc_p;
    float al[5], om[5];
#pragma unroll
    for (int tc = 0; tc < 5; ++tc) {
        float tau = mtc * exp2f(0.5f * (float)(tc - 2));
        al[tc] = expf(-1.0f / tau);
        om[tc] = 1.0f - al[tc];
    }
    float s[5] = {0.f, 0.f, 0.f, 0.f, 0.f};
    for (int t = 0; t < 16; ++t) {
        float acc = 0.f;
#pragma unroll
        for (int tc = 0; tc < 5; ++tc) {
            float v = x[(size_t)((t * 4 + b) * 10 + tc * 2 + c) * HW + p];
            s[tc] = al[tc] * s[tc] + om[tc] * v;
            acc += s[tc];
        }
        z[(size_t)((t * 4 + b) * 2 + c) * HW + p] = acc * 0.2f;
    }
}

// ---------------------------------------------------------------------------
// K2: head conv 2->16 (FFMA f32x2 path)
// ---------------------------------------------------------------------------
template <int CIN>
__global__ __launch_bounds__(256, 2)
void conv15_to16(const float* __restrict__ in, const float* __restrict__ w,
                 float* __restrict__ out) {
    __shared__ __align__(16) float tile[46 * 48];
    __shared__ __align__(16) float wsm[225 * 16];

    int img = blockIdx.y;
    int bx0 = (blockIdx.x & 3)  * 32;
    int by0 = (blockIdx.x >> 2) * 32;
    int tid = threadIdx.x;
    int tx  = tid & 31;
    int ty  = tid >> 5;

    ull acc[4][8];
#pragma unroll
    for (int r = 0; r < 4; ++r)
#pragma unroll
        for (int j = 0; j < 8; ++j) acc[r][j] = 0ull;

    for (int cin = 0; cin < CIN; ++cin) {
        __syncthreads();
        const float* src = in + ((size_t)img * CIN + cin) * HW;
        for (int i = tid; i < 46 * 46; i += 256) {
            int r  = i / 46, cc = i % 46;
            int gy = by0 + r - 7, gx = bx0 + cc - 7;
            float v = 0.f;
            if (gy >= 0 && gy < 128 && gx >= 0 && gx < 128) v = src[gy * 128 + gx];
            tile[r * 48 + cc] = v;
        }
        for (int i = tid; i < 225 * 16; i += 256) {
            int k = i >> 4, co = i & 15;
            wsm[i] = w[((size_t)co * CIN + cin) * 225 + k];
        }
        __syncthreads();

#pragma unroll 1
        for (int ky = 0; ky < 15; ++ky) {
            const float* trow = &tile[(ty + ky) * 48 + tx];
#pragma unroll
            for (int kx = 0; kx < 15; ++kx) {
                ull p0 = pack2(trow[kx],           trow[kx]);
                ull p1 = pack2(trow[kx +  8 * 48], trow[kx +  8 * 48]);
                ull p2 = pack2(trow[kx + 16 * 48], trow[kx + 16 * 48]);
                ull p3 = pack2(trow[kx + 24 * 48], trow[kx + 24 * 48]);
                const ull* wq = (const ull*)&wsm[(ky * 15 + kx) * 16];
#pragma unroll
                for (int j = 0; j < 8; ++j) {
                    ull wv = wq[j];
                    fma2(acc[0][j], p0, wv);
                    fma2(acc[1][j], p1, wv);
                    fma2(acc[2][j], p2, wv);
                    fma2(acc[3][j], p3, wv);
                }
            }
        }
    }

#pragma unroll
    for (int r = 0; r < 4; ++r) {
        int oy = by0 + ty + 8 * r;
#pragma unroll
        for (int j = 0; j < 8; ++j) {
            float lo, hi;
            unpack2(acc[r][j], lo, hi);
            out[((size_t)img * 16 + 2 * j)     * HW + oy * 128 + bx0 + tx] = lo;
            out[((size_t)img * 16 + 2 * j + 1) * HW + oy * 128 + bx0 + tx] = hi;
        }
    }
}

// ---------------------------------------------------------------------------
// K3a: prepass — each (img,y) row becomes 144 pixel records of 48B:
// [16 fp16 (32B) | 16B pad(0)]. 3-unit stride => conflict-free ldmatrix.
// ---------------------------------------------------------------------------
__global__ __launch_bounds__(160, 4)
void split_rows(const float* __restrict__ in, uint8_t* __restrict__ xs) {
    __shared__ __align__(16) uint8_t rowbuf[144 * 48];
    int y = blockIdx.x, img = blockIdx.y;
    int p = threadIdx.x;

    if (p < 144) {
        int x = p - 7;
        bool valid = (x >= 0 && x < 128);
        __align__(16) __half h[16];
#pragma unroll
        for (int c = 0; c < 16; ++c) {
            float a = valid ? in[((size_t)(img * 16 + c) * 128 + y) * 128 + x] : 0.f;
            h[c] = __float2half_rn(a);
        }
        uint8_t* rb = rowbuf + p * 48;
        *(uint4*)(rb +  0) = *(const uint4*)&h[0];
        *(uint4*)(rb + 16) = *(const uint4*)&h[8];
        *(uint4*)(rb + 32) = make_uint4(0, 0, 0, 0);
    }
    __syncthreads();
    uint8_t* dst = xs + (size_t)(img * 128 + y) * ROWB;
    for (int u = threadIdx.x; u < 432; u += 160)
        *(uint4*)(dst + u * 16) = *(const uint4*)(rowbuf + u * 16);
}

// ---------------------------------------------------------------------------
// K3b: prepass — fp16 weights (x1024 to dodge denormals) into per-(ky,kx)
// 768B blocks: [co 16 rows x 48B stride], 2B halves at cin*2. Conflict-free.
// ---------------------------------------------------------------------------
__global__ void split_weights(const float* __restrict__ w, uint8_t* __restrict__ ws) {
    int kxy = blockIdx.x;            // 0..224
    int t   = threadIdx.x;           // 0..255
    int co  = t >> 4, cin = t & 15;
    int ky  = kxy / 15, kx = kxy % 15;
    float wv = w[((size_t)(co * 16 + cin) * 15 + ky) * 15 + kx] * 1024.0f;
    uint8_t* blk = ws + (size_t)kxy * 768;
    *(__half*)(blk + co * 48 + cin * 2) = __float2half_rn(wv);
    if (cin == 0) *(uint4*)(blk + co * 48 + 32) = make_uint4(0, 0, 0, 0); // pad
}

// ---------------------------------------------------------------------------
// K4: sq1 conv 16->16 via fp16 HMMA, software-pipelined kx loop.
// CTA = (image, 4 output rows); 8 warps = (row, x-half), 4 M-tiles each.
// B double-buffered in smem; fragment double-buffer in registers.
// ---------------------------------------------------------------------------
__global__ __launch_bounds__(256, 1)
void conv_sq1_hmma(const uint8_t* __restrict__ xs, const uint8_t* __restrict__ ws,
                   float* __restrict__ out) {
    extern __shared__ __align__(16) uint8_t sm[];
    uint8_t* Asm = sm;
    uint8_t* Bsm = sm + A_BYTES;     // 2 x B_SLICE

    int tid  = threadIdx.x;
    int lane = tid & 31;
    int w    = tid >> 5;             // warp 0..7
    int r    = w >> 1;               // output row 0..3
    int half = w & 1;                // x half 0..1
    int grp  = blockIdx.x;           // 0..31
    int img  = blockIdx.y;           // 0..63
    int y0   = grp * 4;

    // ---- A ring: 18 input rows (y0-7 .. y0+10), zero-padded at edges ----
    const uint8_t* srcbase = xs + (size_t)img * 128 * ROWB;
    for (int u = tid; u < 18 * 432; u += 256) {
        int slot = u / 432, q = u % 432;
        int yin  = y0 - 7 + slot;
        uint4 v = make_uint4(0, 0, 0, 0);
        if (yin >= 0 && yin < 128)
            v = *(const uint4*)(srcbase + (size_t)yin * ROWB + q * 16);
        *(uint4*)(Asm + slot * ROWB + q * 16) = v;
    }
    // ---- preload B slice ky=0 into buffer 0 ----
    for (int u = tid; u < 720; u += 256)
        *(uint4*)(Bsm + u * 16) = *(const uint4*)(ws + u * 16);

    uint32_t asm_base = smem_u32(Asm);
    uint32_t bsm_base = smem_u32(Bsm);
    int part = lane >> 3, rr = lane & 7;
    uint32_t a_off = (uint32_t)((((part & 1) << 3) + rr) * 48 + ((part >> 1) << 4));
    uint32_t b_off = (uint32_t)((((part >> 1) << 3) + rr) * 48 + ((part & 1) << 4));

    float acc[4][2][4];
#pragma unroll
    for (int t = 0; t < 4; ++t)
#pragma unroll
        for (int h = 0; h < 2; ++h)
#pragma unroll
            for (int i = 0; i < 4; ++i) acc[t][h][i] = 0.f;

    __syncthreads();

#pragma unroll 1
    for (int ky = 0; ky < 15; ++ky) {
        if (ky) __syncthreads();
        if (ky < 14) {                           // prefetch next B slice (gmem)
            const uint8_t* bw = ws + (size_t)(ky + 1) * B_SLICE;
            uint8_t* bdst = Bsm + ((ky + 1) & 1) * B_SLICE;
            for (int u = tid; u < 720; u += 256)
                *(uint4*)(bdst + u * 16) = *(const uint4*)(bw + u * 16);
        }
        uint32_t bcur = bsm_base + (uint32_t)((ky & 1) * B_SLICE) + b_off;
        uint32_t arow = asm_base + (uint32_t)((r + ky) * ROWB) + a_off
                      + (uint32_t)(half * 4 * 768);

        // ---- software-pipelined kx loop: double-buffered fragments ----
        uint32_t B[2][4], A[2][4][4];
        ldsm4(B[0], bcur);
#pragma unroll
        for (int t = 0; t < 4; ++t) ldsm4(A[0][t], arow + t * 768);

#pragma unroll
        for (int kx = 0; kx < 15; ++kx) {
            int cur = kx & 1, nxt = cur ^ 1;
            if (kx < 14) {
                ldsm4(B[nxt], bcur + (kx + 1) * 768);
                uint32_t an = arow + (kx + 1) * 48;
#pragma unroll
                for (int t = 0; t < 4; ++t) ldsm4(A[nxt][t], an + t * 768);
            }
#pragma unroll
            for (int t = 0; t < 4; ++t) {
                mma_f16(acc[t][0], A[cur][t], B[cur][0], B[cur][1]);
                mma_f16(acc[t][1], A[cur][t], B[cur][2], B[cur][3]);
            }
        }
    }

    // ---- epilogue: scale back 2^-10, stage in smem, coalesced stores ----
    __syncthreads();
    float* stage = (float*)Asm;                  // 32KB needed, fits in A ring
    {
        const float sc = 1.0f / 1024.0f;
        int q  = lane >> 2;
        int cb = (lane & 3) * 2;
#pragma unroll
        for (int t = 0; t < 4; ++t) {
            int tt = half * 4 + t;
            int x  = tt * 16 + q;
#pragma unroll
            for (int h = 0; h < 2; ++h) {
                int co = h * 8 + cb;
                stage[(r * 16 + co)     * 128 + x    ] = acc[t][h][0] * sc;
                stage[(r * 16 + co + 1) * 128 + x    ] = acc[t][h][1] * sc;
                stage[(r * 16 + co)     * 128 + x + 8] = acc[t][h][2] * sc;
                stage[(r * 16 + co + 1) * 128 + x + 8] = acc[t][h][3] * sc;
            }
        }
    }
    __syncthreads();
    for (int i = tid; i < 2048; i += 256) {
        int rw  = i >> 9;
        int rem = i & 511;
        int co  = rem >> 5;
        int x4  = rem & 31;
        float4 v = *(const float4*)&stage[(rw * 16 + co) * 128 + x4 * 4];
        *(float4*)&out[((size_t)(img * 16 + co) * 128 + (y0 + rw)) * 128 + x4 * 4] = v;
    }
}

// ---------------------------------------------------------------------------
// K5: 15x15 conv 16 -> 1 fused with 2x2 max pool. Row-reuse: each thread
// computes 4x * 2y outputs; each loaded row window feeds both y-rows.
// ---------------------------------------------------------------------------
__global__ __launch_bounds__(256, 2)
void conv_sq2_pool(const float* __restrict__ in, const float* __restrict__ w,
                   float* __restrict__ out) {
    __shared__ __align__(16) float tile[78 * 48];
    __shared__ __align__(16) ull  wsm2[225];
    __shared__ float ctile[64 * 32];

    int img = blockIdx.y;
    int bx0 = (blockIdx.x & 3)  * 32;
    int by0 = (blockIdx.x >> 2) * 64;
    int tid = threadIdx.x;
    int tx  = tid & 7;
    int tyg = tid >> 3;

    ull acc[2][2];
    acc[0][0] = acc[0][1] = acc[1][0] = acc[1][1] = 0ull;

    for (int cin = 0; cin < 16; ++cin) {
        __syncthreads();
        const float* src = in + ((size_t)img * 16 + cin) * HW;
        for (int i = tid; i < 78 * 46; i += 256) {
            int rrow = i / 46, cc = i % 46;
            int gy = by0 + rrow - 7, gx = bx0 + cc - 7;
            float v = 0.f;
            if (gy >= 0 && gy < 128 && gx >= 0 && gx < 128) v = src[gy * 128 + gx];
            tile[rrow * 48 + cc] = v;
        }
        if (tid < 225) {
            float wv = w[cin * 225 + tid];
            wsm2[tid] = pack2(wv, wv);
        }
        __syncthreads();

#pragma unroll 1
        for (int s = 0; s < 16; ++s) {
            int trow = tyg * 2 + s;
            const float4* tp = (const float4*)&tile[trow * 48 + 4 * tx];
            float4 v0 = tp[0], v1 = tp[1], v2 = tp[2], v3 = tp[3], v4 = tp[4];
            float rv[20] = {v0.x, v0.y, v0.z, v0.w, v1.x, v1.y, v1.z, v1.w,
                            v2.x, v2.y, v2.z, v2.w, v3.x, v3.y, v3.z, v3.w,
                            v4.x, v4.y, v4.z, v4.w};
            ull pr[17];
#pragma unroll
            for (int k = 0; k < 17; ++k) pr[k] = pack2(rv[k], rv[k + 1]);
            if (s < 15) {
                const ull* wrow = &wsm2[s * 15];
#pragma unroll
                for (int kx = 0; kx < 15; ++kx) {
                    ull wv = wrow[kx];
                    fma2(acc[0][0], pr[kx],     wv);
                    fma2(acc[0][1], pr[kx + 2], wv);
                }
            }
            if (s >= 1) {
                const ull* wrow = &wsm2[(s - 1) * 15];
#pragma unroll
                for (int kx = 0; kx < 15; ++kx) {
                    ull wv = wrow[kx];
                    fma2(acc[1][0], pr[kx],     wv);
                    fma2(acc[1][1], pr[kx + 2], wv);
                }
            }
        }
    }

    __syncthreads();
#pragma unroll
    for (int r = 0; r < 2; ++r) {
        float o0, o1, o2, o3;
        unpack2(acc[r][0], o0, o1);
        unpack2(acc[r][1], o2, o3);
        float* cr = &ctile[(tyg * 2 + r) * 32 + 4 * tx];
        cr[0] = o0; cr[1] = o1; cr[2] = o2; cr[3] = o3;
    }
    __syncthreads();

    int px = tid & 15, py0 = tid >> 4;
#pragma unroll
    for (int hh = 0; hh < 2; ++hh) {
        int py = py0 + hh * 16;
        float m = fmaxf(fmaxf(ctile[(2 * py) * 32 + 2 * px],     ctile[(2 * py) * 32 + 2 * px + 1]),
                        fmaxf(ctile[(2 * py + 1) * 32 + 2 * px], ctile[(2 * py + 1) * 32 + 2 * px + 1]));
        out[(size_t)img * 4096 + (by0 / 2 + py) * 64 + (bx0 / 2 + px)] = m;
    }
}

// ---------------------------------------------------------------------------
// K6: softmax over 64x64 heatmap + soft-argmax. One block per image.
// ---------------------------------------------------------------------------
__global__ void softargmax_kernel(const float* __restrict__ heat,
                                  float* __restrict__ coords) {
    __shared__ float red[256];
    int img = blockIdx.x, tid = threadIdx.x;
    const float* h = heat + (size_t)img * 4096;

    float v[16];
    float m = -1e30f;
#pragma unroll
    for (int i = 0; i < 16; ++i) { v[i] = h[tid + 256 * i]; m = fmaxf(m, v[i]); }

    red[tid] = m; __syncthreads();
    for (int s = 128; s > 0; s >>= 1) {
        if (tid < s) red[tid] = fmaxf(red[tid], red[tid + s]);
        __syncthreads();
    }
    m = red[0]; __syncthreads();

    float se = 0.f, sx = 0.f, sy = 0.f;
#pragma unroll
    for (int i = 0; i < 16; ++i) {
        int k = tid + 256 * i;
        float e = expf(v[i] - m);
        se += e;
        sx += e * (float)(k & 63);
        sy += e * (float)(k >> 6);
    }

    red[tid] = se; __syncthreads();
    for (int s = 128; s > 0; s >>= 1) { if (tid < s) red[tid] += red[tid + s]; __syncthreads(); }
    float tot = red[0]; __syncthreads();

    red[tid] = sx; __syncthreads();
    for (int s = 128; s > 0; s >>= 1) { if (tid < s) red[tid] += red[tid + s]; __syncthreads(); }
    float totx = red[0]; __syncthreads();

    red[tid] = sy; __syncthreads();
    for (int s = 128; s > 0; s >>= 1) { if (tid < s) red[tid] += red[tid + s]; __syncthreads(); }
    float toty = red[0];

    if (tid == 0) {
        coords[img * 2 + 0] = totx / (63.0f * tot);
        coords[img * 2 + 1] = toty / (63.0f * tot);
    }
}

// ---------------------------------------------------------------------------
extern "C" void kernel_launch(void* const* d_in, const int* in_sizes, int n_in,
                              void* d_out, int out_size) {
    const float* x      = (const float*)d_in[0];
    const float* head_w = (const float*)d_in[1];
    const float* sq1_w  = (const float*)d_in[2];
    const float* sq2_w  = (const float*)d_in[3];
    const float* mtc    = (const float*)d_in[4];
    float* out = (float*)d_out;

    float *zp, *xmp, *h1p;
    uint8_t *xsp, *wsp;
    cudaGetSymbolAddress((void**)&zp,  g_z);
    cudaGetSymbolAddress((void**)&xmp, g_xm);
    cudaGetSymbolAddress((void**)&h1p, g_h1);
    cudaGetSymbolAddress((void**)&xsp, g_xs);
    cudaGetSymbolAddress((void**)&wsp, g_ws);

    cudaFuncSetAttribute(conv_sq1_hmma,
                         cudaFuncAttributeMaxDynamicSharedMemorySize, SQ1_SMEM);

    integrate_kernel<<<512, 256>>>(x, mtc, zp);
    split_weights<<<225, 256>>>(sq1_w, wsp);
    conv15_to16<2><<<dim3(16, NIMG), 256>>>(zp, head_w, xmp);
    split_rows<<<dim3(128, NIMG), 160>>>(xmp, xsp);
    conv_sq1_hmma<<<dim3(32, NIMG), 256, SQ1_SMEM>>>(xsp, wsp, h1p);
    conv_sq2_pool<<<dim3(8, NIMG), 256>>>(h1p, sq2_w, out);

    if (out_size >= NIMG * 4096 + NIMG * 2) {
        softargmax_kernel<<<NIMG, 256>>>(out, out + (size_t)NIMG * 4096);
    }
}

// round 11
// speedup vs baseline: 1.0753x; 1.0753x over previous
#include <cuda_runtime.h>
#include <cuda_bf16.h>
#include <cuda_fp16.h>
#include <math.h>
#include <stdint.h>

#define NIMG 64          // T*B = 16*4
#define HW   16384       // 128*128
typedef unsigned long long ull;

// Scratch (allocation-free rule: __device__ globals; zero-init at load)
__device__ float   g_z [NIMG *  2 * HW];                 //  8 MB integrated input
__device__ float   g_h1[NIMG * 16 * HW];                 // 64 MB sq1 conv output
__device__ uint8_t g_xs[(size_t)NIMG * 128 * 144 * 48];  // 56.6 MB fp16 pixel rows (sq1 A)
__device__ uint8_t g_hz[(size_t)NIMG * 128 * 128 * 64];  // 67 MB head A records
__device__ uint8_t g_ws[225 * 768];                      // sq1 fp16 weights (x1024)
__device__ uint8_t g_hw[15 * 1280];                      // head fp16 weights per-ky

#define ROWB 6912                        // sq1: 144 px * 48 B
#define A_BYTES (18 * ROWB)              // 124416
#define B_SLICE 11520                    // 15 kx * 768
#define SQ1_SMEM (A_BYTES + 2 * B_SLICE) // 147456

#define HROWB 8192                       // head: 128 recs * 64 B
#define H_A_BYTES (22 * HROWB)           // 180224
#define H_SMEM (H_A_BYTES + 15 * 1280)   // 199424

// ---- f32x2 helpers --------------------------------------------------------
__device__ __forceinline__ void fma2(ull& d, ull a, ull b) {
    asm("fma.rn.f32x2 %0, %1, %2, %0;" : "+l"(d) : "l"(a), "l"(b));
}
__device__ __forceinline__ ull pack2(float lo, float hi) {
    ull r; asm("mov.b64 %0, {%1, %2};" : "=l"(r) : "f"(lo), "f"(hi)); return r;
}
__device__ __forceinline__ void unpack2(ull v, float& lo, float& hi) {
    asm("mov.b64 {%0, %1}, %2;" : "=f"(lo), "=f"(hi) : "l"(v));
}

// ---- HMMA helpers ---------------------------------------------------------
__device__ __forceinline__ uint32_t smem_u32(const void* p) {
    uint32_t a;
    asm("{ .reg .u64 t; cvta.to.shared.u64 t, %1; cvt.u32.u64 %0, t; }" : "=r"(a) : "l"(p));
    return a;
}
__device__ __forceinline__ void ldsm4(uint32_t* r, uint32_t a) {
    asm volatile("ldmatrix.sync.aligned.m8n8.x4.shared.b16 {%0,%1,%2,%3}, [%4];"
                 : "=r"(r[0]), "=r"(r[1]), "=r"(r[2]), "=r"(r[3]) : "r"(a));
}
__device__ __forceinline__ void mma_f16(float* d, const uint32_t* a,
                                        uint32_t b0, uint32_t b1) {
    asm volatile(
        "mma.sync.aligned.m16n8k16.row.col.f32.f16.f16.f32 "
        "{%0,%1,%2,%3}, {%4,%5,%6,%7}, {%8,%9}, {%0,%1,%2,%3};"
        : "+f"(d[0]), "+f"(d[1]), "+f"(d[2]), "+f"(d[3])
        : "r"(a[0]), "r"(a[1]), "r"(a[2]), "r"(a[3]), "r"(b0), "r"(b1));
}

// ---------------------------------------------------------------------------
// K1: leaky integration over T per TC slice + mean over TC.
// ---------------------------------------------------------------------------
__global__ void integrate_kernel(const float* __restrict__ x,
                                 const float* __restrict__ mtc_p,
                                 float* __restrict__ z) {
    int idx = blockIdx.x * blockDim.x + threadIdx.x;
    if (idx >= 4 * 2 * HW) return;
    int p  = idx & (HW - 1);
    int bc = idx >> 14;
    int c  = bc & 1;
    int b  = bc >> 1;

    float mtc = *mtc_p;
    float al[5], om[5];
#pragma unroll
    for (int tc = 0; tc < 5; ++tc) {
        float tau = mtc * exp2f(0.5f * (float)(tc - 2));
        al[tc] = expf(-1.0f / tau);
        om[tc] = 1.0f - al[tc];
    }
    float s[5] = {0.f, 0.f, 0.f, 0.f, 0.f};
    for (int t = 0; t < 16; ++t) {
        float acc = 0.f;
#pragma unroll
        for (int tc = 0; tc < 5; ++tc) {
            float v = x[(size_t)((t * 4 + b) * 10 + tc * 2 + c) * HW + p];
            s[tc] = al[tc] * s[tc] + om[tc] * v;
            acc += s[tc];
        }
        z[(size_t)((t * 4 + b) * 2 + c) * HW + p] = acc * 0.2f;
    }
}

// ---------------------------------------------------------------------------
// K2a: head A-record prepass. Per (img,y): 128 records of 64B:
// rec[x][k=(kx*2+c)] = fp16(zpad[y][x+kx-7][c]), kx 0..14 real, 15 pad.
// ---------------------------------------------------------------------------
__global__ __launch_bounds__(128, 8)
void head_recs(const float* __restrict__ z, uint8_t* __restrict__ hz) {
    __shared__ float zrow[2][128];
    int y = blockIdx.x, img = blockIdx.y;
    int x = threadIdx.x;
    zrow[0][x] = z[((size_t)(img * 2 + 0) * 128 + y) * 128 + x];
    zrow[1][x] = z[((size_t)(img * 2 + 1) * 128 + y) * 128 + x];
    __syncthreads();

    __align__(16) __half h[32];
#pragma unroll
    for (int kx = 0; kx < 16; ++kx) {
        int xi = x + kx - 7;
        bool v = (kx < 15) && (xi >= 0) && (xi < 128);
        h[kx * 2 + 0] = v ? __float2half_rn(zrow[0][xi]) : __half(0.f);
        h[kx * 2 + 1] = v ? __float2half_rn(zrow[1][xi]) : __half(0.f);
    }
    uint8_t* dst = hz + ((size_t)(img * 128 + y) * 128 + x) * 64;
    *(uint4*)(dst +  0) = *(const uint4*)&h[0];
    *(uint4*)(dst + 16) = *(const uint4*)&h[8];
    *(uint4*)(dst + 32) = *(const uint4*)&h[16];
    *(uint4*)(dst + 48) = *(const uint4*)&h[24];
}

// ---------------------------------------------------------------------------
// K2b: head weight prepass. Per ky: 1280B block, co row (80B stride):
// b16[k=(kx*2+c)] = fp16(head_w[co][c][ky][kx]), kx 15 pad; bytes 64..79 = 0.
// ---------------------------------------------------------------------------
__global__ void head_ws(const float* __restrict__ w, uint8_t* __restrict__ hw) {
    int ky = blockIdx.x;             // 0..14
    int t  = threadIdx.x;            // 0..511
    int co = t >> 5, k = t & 31;
    int kx = k >> 1, c = k & 1;
    float wv = (kx < 15) ? w[((size_t)(co * 2 + c) * 15 + ky) * 15 + kx] : 0.f;
    uint8_t* blk = hw + (size_t)ky * 1280;
    *(__half*)(blk + co * 80 + k * 2) = __float2half_rn(wv);
    if (k == 0) *(uint4*)(blk + co * 80 + 64) = make_uint4(0, 0, 0, 0);
}

// ---------------------------------------------------------------------------
// K2c: head conv 2->16 via fp16 HMMA implicit GEMM (K=(kx,c)=32 per ky).
// CTA = (image, 8 output rows); 8 warps = 1 row each, 8 M-tiles.
// Epilogue writes g_xs fp16 records directly (border records stay zero).
// ---------------------------------------------------------------------------
__global__ __launch_bounds__(256, 1)
void conv_head_hmma(const uint8_t* __restrict__ hz, const uint8_t* __restrict__ hw,
                    uint8_t* __restrict__ xs) {
    extern __shared__ __align__(16) uint8_t sm[];
    uint8_t* Asm = sm;
    uint8_t* Bsm = sm + H_A_BYTES;

    int tid  = threadIdx.x;
    int lane = tid & 31;
    int r    = tid >> 5;             // warp 0..7 = output row
    int grp  = blockIdx.x;           // 0..15
    int img  = blockIdx.y;           // 0..63
    int y0   = grp * 8;

    // ---- A ring: 22 record rows (y0-7 .. y0+14), zero-padded ----
    const uint8_t* srcbase = hz + (size_t)img * 128 * HROWB;
    for (int u = tid; u < 22 * 512; u += 256) {
        int slot = u >> 9, q = u & 511;
        int yin  = y0 - 7 + slot;
        uint4 v = make_uint4(0, 0, 0, 0);
        if (yin >= 0 && yin < 128)
            v = *(const uint4*)(srcbase + (size_t)yin * HROWB + q * 16);
        *(uint4*)(Asm + slot * HROWB + q * 16) = v;
    }
    // ---- all 15 B blocks ----
    for (int u = tid; u < 1200; u += 256)
        *(uint4*)(Bsm + u * 16) = *(const uint4*)(hw + u * 16);

    uint32_t asm_base = smem_u32(Asm);
    uint32_t bsm_base = smem_u32(Bsm);
    int part = lane >> 3, rr = lane & 7;
    uint32_t a_off = (uint32_t)((((part & 1) << 3) + rr) * 64 + ((part >> 1) << 4));
    uint32_t b_off = (uint32_t)((((part >> 1) << 3) + rr) * 80 + ((part & 1) << 4));

    float acc[8][2][4];
#pragma unroll
    for (int t = 0; t < 8; ++t)
#pragma unroll
        for (int h = 0; h < 2; ++h)
#pragma unroll
            for (int i = 0; i < 4; ++i) acc[t][h][i] = 0.f;

    __syncthreads();

#pragma unroll 1
    for (int ky = 0; ky < 15; ++ky) {
        uint32_t bb = bsm_base + (uint32_t)(ky * 1280) + b_off;
        uint32_t B0[4], B1[4];
        ldsm4(B0, bb);
        ldsm4(B1, bb + 32);
        uint32_t arow = asm_base + (uint32_t)((r + ky) * HROWB) + a_off;
#pragma unroll
        for (int t = 0; t < 8; ++t) {
            uint32_t A0[4], A1[4];
            ldsm4(A0, arow + t * 1024);        // k chunk 0 (bytes 0..31)
            ldsm4(A1, arow + t * 1024 + 32);   // k chunk 1 (bytes 32..63)
            mma_f16(acc[t][0], A0, B0[0], B0[1]);
            mma_f16(acc[t][1], A0, B0[2], B0[3]);
            mma_f16(acc[t][0], A1, B1[0], B1[1]);
            mma_f16(acc[t][1], A1, B1[2], B1[3]);
        }
    }

    // ---- epilogue: stage fp32 in smem, then write g_xs fp16 records ----
    __syncthreads();
    float* stage = (float*)Asm;                // [8 rows][16 co][128 x] = 64KB
    {
        int q  = lane >> 2;
        int cb = (lane & 3) * 2;
#pragma unroll
        for (int t = 0; t < 8; ++t) {
            int x = t * 16 + q;
#pragma unroll
            for (int h = 0; h < 2; ++h) {
                int co = h * 8 + cb;
                stage[(r * 16 + co)     * 128 + x    ] = acc[t][h][0];
                stage[(r * 16 + co + 1) * 128 + x    ] = acc[t][h][1];
                stage[(r * 16 + co)     * 128 + x + 8] = acc[t][h][2];
                stage[(r * 16 + co + 1) * 128 + x + 8] = acc[t][h][3];
            }
        }
    }
    __syncthreads();
    for (int i = tid; i < 1024; i += 256) {    // 8 rows x 128 px
        int rw = i >> 7, x = i & 127;
        __align__(16) __half h[16];
#pragma unroll
        for (int c = 0; c < 16; ++c)
            h[c] = __float2half_rn(stage[(rw * 16 + c) * 128 + x]);
        uint8_t* dst = xs + (size_t)(img * 128 + y0 + rw) * ROWB + (x + 7) * 48;
        *(uint4*)(dst +  0) = *(const uint4*)&h[0];
        *(uint4*)(dst + 16) = *(const uint4*)&h[8];
        *(uint4*)(dst + 32) = make_uint4(0, 0, 0, 0);
    }
}

// ---------------------------------------------------------------------------
// K3: prepass — sq1 fp16 weights (x1024) into per-(ky,kx) 768B blocks.
// ---------------------------------------------------------------------------
__global__ void split_weights(const float* __restrict__ w, uint8_t* __restrict__ ws) {
    int kxy = blockIdx.x;            // 0..224
    int t   = threadIdx.x;           // 0..255
    int co  = t >> 4, cin = t & 15;
    int ky  = kxy / 15, kx = kxy % 15;
    float wv = w[((size_t)(co * 16 + cin) * 15 + ky) * 15 + kx] * 1024.0f;
    uint8_t* blk = ws + (size_t)kxy * 768;
    *(__half*)(blk + co * 48 + cin * 2) = __float2half_rn(wv);
    if (cin == 0) *(uint4*)(blk + co * 48 + 32) = make_uint4(0, 0, 0, 0);
}

// ---------------------------------------------------------------------------
// K4: sq1 conv 16->16 via fp16 HMMA (at legacy-HMMA tensor floor).
// ---------------------------------------------------------------------------
__global__ __launch_bounds__(256, 1)
void conv_sq1_hmma(const uint8_t* __restrict__ xs, const uint8_t* __restrict__ ws,
                   float* __restrict__ out) {
    extern __shared__ __align__(16) uint8_t sm[];
    uint8_t* Asm = sm;
    uint8_t* Bsm = sm + A_BYTES;

    int tid  = threadIdx.x;
    int lane = tid & 31;
    int w    = tid >> 5;
    int r    = w >> 1;
    int half = w & 1;
    int grp  = blockIdx.x;
    int img  = blockIdx.y;
    int y0   = grp * 4;

    const uint8_t* srcbase = xs + (size_t)img * 128 * ROWB;
    for (int u = tid; u < 18 * 432; u += 256) {
        int slot = u / 432, q = u % 432;
        int yin  = y0 - 7 + slot;
        uint4 v = make_uint4(0, 0, 0, 0);
        if (yin >= 0 && yin < 128)
            v = *(const uint4*)(srcbase + (size_t)yin * ROWB + q * 16);
        *(uint4*)(Asm + slot * ROWB + q * 16) = v;
    }
    for (int u = tid; u < 720; u += 256)
        *(uint4*)(Bsm + u * 16) = *(const uint4*)(ws + u * 16);

    uint32_t asm_base = smem_u32(Asm);
    uint32_t bsm_base = smem_u32(Bsm);
    int part = lane >> 3, rr = lane & 7;
    uint32_t a_off = (uint32_t)((((part & 1) << 3) + rr) * 48 + ((part >> 1) << 4));
    uint32_t b_off = (uint32_t)((((part >> 1) << 3) + rr) * 48 + ((part & 1) << 4));

    float acc[4][2][4];
#pragma unroll
    for (int t = 0; t < 4; ++t)
#pragma unroll
        for (int h = 0; h < 2; ++h)
#pragma unroll
            for (int i = 0; i < 4; ++i) acc[t][h][i] = 0.f;

    __syncthreads();

#pragma unroll 1
    for (int ky = 0; ky < 15; ++ky) {
        if (ky) __syncthreads();
        if (ky < 14) {
            const uint8_t* bw = ws + (size_t)(ky + 1) * B_SLICE;
            uint8_t* bdst = Bsm + ((ky + 1) & 1) * B_SLICE;
            for (int u = tid; u < 720; u += 256)
                *(uint4*)(bdst + u * 16) = *(const uint4*)(bw + u * 16);
        }
        uint32_t bcur = bsm_base + (uint32_t)((ky & 1) * B_SLICE) + b_off;
        uint32_t arow = asm_base + (uint32_t)((r + ky) * ROWB) + a_off
                      + (uint32_t)(half * 4 * 768);

        uint32_t B[2][4], A[2][4][4];
        ldsm4(B[0], bcur);
#pragma unroll
        for (int t = 0; t < 4; ++t) ldsm4(A[0][t], arow + t * 768);

#pragma unroll
        for (int kx = 0; kx < 15; ++kx) {
            int cur = kx & 1, nxt = cur ^ 1;
            if (kx < 14) {
                ldsm4(B[nxt], bcur + (kx + 1) * 768);
                uint32_t an = arow + (kx + 1) * 48;
#pragma unroll
                for (int t = 0; t < 4; ++t) ldsm4(A[nxt][t], an + t * 768);
            }
#pragma unroll
            for (int t = 0; t < 4; ++t) {
                mma_f16(acc[t][0], A[cur][t], B[cur][0], B[cur][1]);
                mma_f16(acc[t][1], A[cur][t], B[cur][2], B[cur][3]);
            }
        }
    }

    __syncthreads();
    float* stage = (float*)Asm;
    {
        const float sc = 1.0f / 1024.0f;
        int q  = lane >> 2;
        int cb = (lane & 3) * 2;
#pragma unroll
        for (int t = 0; t < 4; ++t) {
            int tt = half * 4 + t;
            int x  = tt * 16 + q;
#pragma unroll
            for (int h = 0; h < 2; ++h) {
                int co = h * 8 + cb;
                stage[(r * 16 + co)     * 128 + x    ] = acc[t][h][0] * sc;
                stage[(r * 16 + co + 1) * 128 + x    ] = acc[t][h][1] * sc;
                stage[(r * 16 + co)     * 128 + x + 8] = acc[t][h][2] * sc;
                stage[(r * 16 + co + 1) * 128 + x + 8] = acc[t][h][3] * sc;
            }
        }
    }
    __syncthreads();
    for (int i = tid; i < 2048; i += 256) {
        int rw  = i >> 9;
        int rem = i & 511;
        int co  = rem >> 5;
        int x4  = rem & 31;
        float4 v = *(const float4*)&stage[(rw * 16 + co) * 128 + x4 * 4];
        *(float4*)&out[((size_t)(img * 16 + co) * 128 + (y0 + rw)) * 128 + x4 * 4] = v;
    }
}

// ---------------------------------------------------------------------------
// K5: 15x15 conv 16 -> 1 fused with 2x2 max pool (f32x2, row-reuse).
// ---------------------------------------------------------------------------
__global__ __launch_bounds__(256, 2)
void conv_sq2_pool(const float* __restrict__ in, const float* __restrict__ w,
                   float* __restrict__ out) {
    __shared__ __align__(16) float tile[78 * 48];
    __shared__ __align__(16) ull  wsm2[225];
    __shared__ float ctile[64 * 32];

    int img = blockIdx.y;
    int bx0 = (blockIdx.x & 3)  * 32;
    int by0 = (blockIdx.x >> 2) * 64;
    int tid = threadIdx.x;
    int tx  = tid & 7;
    int tyg = tid >> 3;

    ull acc[2][2];
    acc[0][0] = acc[0][1] = acc[1][0] = acc[1][1] = 0ull;

    for (int cin = 0; cin < 16; ++cin) {
        __syncthreads();
        const float* src = in + ((size_t)img * 16 + cin) * HW;
        for (int i = tid; i < 78 * 46; i += 256) {
            int rrow = i / 46, cc = i % 46;
            int gy = by0 + rrow - 7, gx = bx0 + cc - 7;
            float v = 0.f;
            if (gy >= 0 && gy < 128 && gx >= 0 && gx < 128) v = src[gy * 128 + gx];
            tile[rrow * 48 + cc] = v;
        }
        if (tid < 225) {
            float wv = w[cin * 225 + tid];
            wsm2[tid] = pack2(wv, wv);
        }
        __syncthreads();

#pragma unroll 1
        for (int s = 0; s < 16; ++s) {
            int trow = tyg * 2 + s;
            const float4* tp = (const float4*)&tile[trow * 48 + 4 * tx];
            float4 v0 = tp[0], v1 = tp[1], v2 = tp[2], v3 = tp[3], v4 = tp[4];
            float rv[20] = {v0.x, v0.y, v0.z, v0.w, v1.x, v1.y, v1.z, v1.w,
                            v2.x, v2.y, v2.z, v2.w, v3.x, v3.y, v3.z, v3.w,
                            v4.x, v4.y, v4.z, v4.w};
            ull pr[17];
#pragma unroll
            for (int k = 0; k < 17; ++k) pr[k] = pack2(rv[k], rv[k + 1]);
            if (s < 15) {
                const ull* wrow = &wsm2[s * 15];
#pragma unroll
                for (int kx = 0; kx < 15; ++kx) {
                    ull wv = wrow[kx];
                    fma2(acc[0][0], pr[kx],     wv);
                    fma2(acc[0][1], pr[kx + 2], wv);
                }
            }
            if (s >= 1) {
                const ull* wrow = &wsm2[(s - 1) * 15];
#pragma unroll
                for (int kx = 0; kx < 15; ++kx) {
                    ull wv = wrow[kx];
                    fma2(acc[1][0], pr[kx],     wv);
                    fma2(acc[1][1], pr[kx + 2], wv);
                }
            }
        }
    }

    __syncthreads();
#pragma unroll
    for (int r = 0; r < 2; ++r) {
        float o0, o1, o2, o3;
        unpack2(acc[r][0], o0, o1);
        unpack2(acc[r][1], o2, o3);
        float* cr = &ctile[(tyg * 2 + r) * 32 + 4 * tx];
        cr[0] = o0; cr[1] = o1; cr[2] = o2; cr[3] = o3;
    }
    __syncthreads();

    int px = tid & 15, py0 = tid >> 4;
#pragma unroll
    for (int hh = 0; hh < 2; ++hh) {
        int py = py0 + hh * 16;
        float m = fmaxf(fmaxf(ctile[(2 * py) * 32 + 2 * px],     ctile[(2 * py) * 32 + 2 * px + 1]),
                        fmaxf(ctile[(2 * py + 1) * 32 + 2 * px], ctile[(2 * py + 1) * 32 + 2 * px + 1]));
        out[(size_t)img * 4096 + (by0 / 2 + py) * 64 + (bx0 / 2 + px)] = m;
    }
}

// ---------------------------------------------------------------------------
// K6: softmax over 64x64 heatmap + soft-argmax. One block per image.
// ---------------------------------------------------------------------------
__global__ void softargmax_kernel(const float* __restrict__ heat,
                                  float* __restrict__ coords) {
    __shared__ float red[256];
    int img = blockIdx.x, tid = threadIdx.x;
    const float* h = heat + (size_t)img * 4096;

    float v[16];
    float m = -1e30f;
#pragma unroll
    for (int i = 0; i < 16; ++i) { v[i] = h[tid + 256 * i]; m = fmaxf(m, v[i]); }

    red[tid] = m; __syncthreads();
    for (int s = 128; s > 0; s >>= 1) {
        if (tid < s) red[tid] = fmaxf(red[tid], red[tid + s]);
        __syncthreads();
    }
    m = red[0]; __syncthreads();

    float se = 0.f, sx = 0.f, sy = 0.f;
#pragma unroll
    for (int i = 0; i < 16; ++i) {
        int k = tid + 256 * i;
        float e = expf(v[i] - m);
        se += e;
        sx += e * (float)(k & 63);
        sy += e * (float)(k >> 6);
    }

    red[tid] = se; __syncthreads();
    for (int s = 128; s > 0; s >>= 1) { if (tid < s) red[tid] += red[tid + s]; __syncthreads(); }
    float tot = red[0]; __syncthreads();

    red[tid] = sx; __syncthreads();
    for (int s = 128; s > 0; s >>= 1) { if (tid < s) red[tid] += red[tid + s]; __syncthreads(); }
    float totx = red[0]; __syncthreads();

    red[tid] = sy; __syncthreads();
    for (int s = 128; s > 0; s >>= 1) { if (tid < s) red[tid] += red[tid + s]; __syncthreads(); }
    float toty = red[0];

    if (tid == 0) {
        coords[img * 2 + 0] = totx / (63.0f * tot);
        coords[img * 2 + 1] = toty / (63.0f * tot);
    }
}

// ---------------------------------------------------------------------------
extern "C" void kernel_launch(void* const* d_in, const int* in_sizes, int n_in,
                              void* d_out, int out_size) {
    const float* x      = (const float*)d_in[0];
    const float* head_w = (const float*)d_in[1];
    const float* sq1_w  = (const float*)d_in[2];
    const float* sq2_w  = (const float*)d_in[3];
    const float* mtc    = (const float*)d_in[4];
    float* out = (float*)d_out;

    float *zp, *h1p;
    uint8_t *xsp, *hzp, *wsp, *hwp;
    cudaGetSymbolAddress((void**)&zp,  g_z);
    cudaGetSymbolAddress((void**)&h1p, g_h1);
    cudaGetSymbolAddress((void**)&xsp, g_xs);
    cudaGetSymbolAddress((void**)&hzp, g_hz);
    cudaGetSymbolAddress((void**)&wsp, g_ws);
    cudaGetSymbolAddress((void**)&hwp, g_hw);

    cudaFuncSetAttribute(conv_sq1_hmma,
                         cudaFuncAttributeMaxDynamicSharedMemorySize, SQ1_SMEM);
    cudaFuncSetAttribute(conv_head_hmma,
                         cudaFuncAttributeMaxDynamicSharedMemorySize, H_SMEM);

    integrate_kernel<<<512, 256>>>(x, mtc, zp);
    split_weights<<<225, 256>>>(sq1_w, wsp);
    head_ws<<<15, 512>>>(head_w, hwp);
    head_recs<<<dim3(128, NIMG), 128>>>(zp, hzp);
    conv_head_hmma<<<dim3(16, NIMG), 256, H_SMEM>>>(hzp, hwp, xsp);
    conv_sq1_hmma<<<dim3(32, NIMG), 256, SQ1_SMEM>>>(xsp, wsp, h1p);
    conv_sq2_pool<<<dim3(8, NIMG), 256>>>(h1p, sq2_w, out);

    if (out_size >= NIMG * 4096 + NIMG * 2) {
        softargmax_kernel<<<NIMG, 256>>>(out, out + (size_t)NIMG * 4096);
    }
}

// round 12
// speedup vs baseline: 1.3595x; 1.2644x over previous
#include <cuda_runtime.h>
#include <cuda_bf16.h>
#include <cuda_fp16.h>
#include <math.h>
#include <stdint.h>

#define NIMG 64          // T*B = 16*4
#define HW   16384       // 128*128
typedef unsigned long long ull;

// Scratch (allocation-free rule: __device__ globals; zero-init at load)
__device__ float   g_z [NIMG *  2 * HW];                 //  8 MB integrated input
__device__ uint8_t g_xs [(size_t)NIMG * 128 * 144 * 48]; // 56.6 MB fp16 recs (sq1 A)
__device__ uint8_t g_h1s[(size_t)NIMG * 128 * 144 * 48]; // 56.6 MB fp16 recs (sq2 A)
__device__ uint8_t g_hz[(size_t)NIMG * 128 * 128 * 64];  // 67 MB head A records
__device__ float   g_d [(size_t)NIMG * 128 * 16 * 128];  // 67 MB sq2 D[yi][ky][x]
__device__ uint8_t g_ws[225 * 768];                      // sq1 fp16 weights (x1024)
__device__ uint8_t g_hw[15 * 1280];                      // head fp16 weights per-ky
__device__ uint8_t g_sw[15 * 768];                       // sq2 fp16 weights per-kx (x1024)

#define ROWB 6912                        // 144 px * 48 B
#define A_BYTES (18 * ROWB)              // 124416
#define B_SLICE 11520                    // 15 kx * 768
#define SQ1_SMEM (A_BYTES + 2 * B_SLICE) // 147456

#define HROWB 8192                       // head: 128 recs * 64 B
#define H_A_BYTES (22 * HROWB)           // 180224
#define H_SMEM (H_A_BYTES + 15 * 1280)   // 199424

#define SQ2A_SMEM 66816                  // max(8*ROWB + 15*768, 64KB stage)

// ---- HMMA helpers ---------------------------------------------------------
__device__ __forceinline__ uint32_t smem_u32(const void* p) {
    uint32_t a;
    asm("{ .reg .u64 t; cvta.to.shared.u64 t, %1; cvt.u32.u64 %0, t; }" : "=r"(a) : "l"(p));
    return a;
}
__device__ __forceinline__ void ldsm4(uint32_t* r, uint32_t a) {
    asm volatile("ldmatrix.sync.aligned.m8n8.x4.shared.b16 {%0,%1,%2,%3}, [%4];"
                 : "=r"(r[0]), "=r"(r[1]), "=r"(r[2]), "=r"(r[3]) : "r"(a));
}
__device__ __forceinline__ void mma_f16(float* d, const uint32_t* a,
                                        uint32_t b0, uint32_t b1) {
    asm volatile(
        "mma.sync.aligned.m16n8k16.row.col.f32.f16.f16.f32 "
        "{%0,%1,%2,%3}, {%4,%5,%6,%7}, {%8,%9}, {%0,%1,%2,%3};"
        : "+f"(d[0]), "+f"(d[1]), "+f"(d[2]), "+f"(d[3])
        : "r"(a[0]), "r"(a[1]), "r"(a[2]), "r"(a[3]), "r"(b0), "r"(b1));
}

// ---------------------------------------------------------------------------
// K1: leaky integration over T per TC slice + mean over TC.
// ---------------------------------------------------------------------------
__global__ void integrate_kernel(const float* __restrict__ x,
                                 const float* __restrict__ mtc_p,
                                 float* __restrict__ z) {
    int idx = blockIdx.x * blockDim.x + threadIdx.x;
    if (idx >= 4 * 2 * HW) return;
    int p  = idx & (HW - 1);
    int bc = idx >> 14;
    int c  = bc & 1;
    int b  = bc >> 1;

    float mtc = *mtc_p;
    float al[5], om[5];
#pragma unroll
    for (int tc = 0; tc < 5; ++tc) {
        float tau = mtc * exp2f(0.5f * (float)(tc - 2));
        al[tc] = expf(-1.0f / tau);
        om[tc] = 1.0f - al[tc];
    }
    float s[5] = {0.f, 0.f, 0.f, 0.f, 0.f};
    for (int t = 0; t < 16; ++t) {
        float acc = 0.f;
#pragma unroll
        for (int tc = 0; tc < 5; ++tc) {
            float v = x[(size_t)((t * 4 + b) * 10 + tc * 2 + c) * HW + p];
            s[tc] = al[tc] * s[tc] + om[tc] * v;
            acc += s[tc];
        }
        z[(size_t)((t * 4 + b) * 2 + c) * HW + p] = acc * 0.2f;
    }
}

// ---------------------------------------------------------------------------
// K2a: head A-record prepass. Per (img,y): 128 records of 64B.
// ---------------------------------------------------------------------------
__global__ __launch_bounds__(128, 8)
void head_recs(const float* __restrict__ z, uint8_t* __restrict__ hz) {
    __shared__ float zrow[2][128];
    int y = blockIdx.x, img = blockIdx.y;
    int x = threadIdx.x;
    zrow[0][x] = z[((size_t)(img * 2 + 0) * 128 + y) * 128 + x];
    zrow[1][x] = z[((size_t)(img * 2 + 1) * 128 + y) * 128 + x];
    __syncthreads();

    __align__(16) __half h[32];
#pragma unroll
    for (int kx = 0; kx < 16; ++kx) {
        int xi = x + kx - 7;
        bool v = (kx < 15) && (xi >= 0) && (xi < 128);
        h[kx * 2 + 0] = v ? __float2half_rn(zrow[0][xi]) : __half(0.f);
        h[kx * 2 + 1] = v ? __float2half_rn(zrow[1][xi]) : __half(0.f);
    }
    uint8_t* dst = hz + ((size_t)(img * 128 + y) * 128 + x) * 64;
    *(uint4*)(dst +  0) = *(const uint4*)&h[0];
    *(uint4*)(dst + 16) = *(const uint4*)&h[8];
    *(uint4*)(dst + 32) = *(const uint4*)&h[16];
    *(uint4*)(dst + 48) = *(const uint4*)&h[24];
}

// ---------------------------------------------------------------------------
// K2b: head weight prepass (per ky 1280B block, 80B co rows).
// ---------------------------------------------------------------------------
__global__ void head_ws(const float* __restrict__ w, uint8_t* __restrict__ hw) {
    int ky = blockIdx.x;
    int t  = threadIdx.x;            // 0..511
    int co = t >> 5, k = t & 31;
    int kx = k >> 1, c = k & 1;
    float wv = (kx < 15) ? w[((size_t)(co * 2 + c) * 15 + ky) * 15 + kx] : 0.f;
    uint8_t* blk = hw + (size_t)ky * 1280;
    *(__half*)(blk + co * 80 + k * 2) = __float2half_rn(wv);
    if (k == 0) *(uint4*)(blk + co * 80 + 64) = make_uint4(0, 0, 0, 0);
}

// ---------------------------------------------------------------------------
// K2c: head conv 2->16 via fp16 HMMA. Writes g_xs fp16 records.
// ---------------------------------------------------------------------------
__global__ __launch_bounds__(256, 1)
void conv_head_hmma(const uint8_t* __restrict__ hz, const uint8_t* __restrict__ hw,
                    uint8_t* __restrict__ xs) {
    extern __shared__ __align__(16) uint8_t sm[];
    uint8_t* Asm = sm;
    uint8_t* Bsm = sm + H_A_BYTES;

    int tid  = threadIdx.x;
    int lane = tid & 31;
    int r    = tid >> 5;
    int grp  = blockIdx.x;
    int img  = blockIdx.y;
    int y0   = grp * 8;

    const uint8_t* srcbase = hz + (size_t)img * 128 * HROWB;
    for (int u = tid; u < 22 * 512; u += 256) {
        int slot = u >> 9, q = u & 511;
        int yin  = y0 - 7 + slot;
        uint4 v = make_uint4(0, 0, 0, 0);
        if (yin >= 0 && yin < 128)
            v = *(const uint4*)(srcbase + (size_t)yin * HROWB + q * 16);
        *(uint4*)(Asm + slot * HROWB + q * 16) = v;
    }
    for (int u = tid; u < 1200; u += 256)
        *(uint4*)(Bsm + u * 16) = *(const uint4*)(hw + u * 16);

    uint32_t asm_base = smem_u32(Asm);
    uint32_t bsm_base = smem_u32(Bsm);
    int part = lane >> 3, rr = lane & 7;
    uint32_t a_off = (uint32_t)((((part & 1) << 3) + rr) * 64 + ((part >> 1) << 4));
    uint32_t b_off = (uint32_t)((((part >> 1) << 3) + rr) * 80 + ((part & 1) << 4));

    float acc[8][2][4];
#pragma unroll
    for (int t = 0; t < 8; ++t)
#pragma unroll
        for (int h = 0; h < 2; ++h)
#pragma unroll
            for (int i = 0; i < 4; ++i) acc[t][h][i] = 0.f;

    __syncthreads();

#pragma unroll 1
    for (int ky = 0; ky < 15; ++ky) {
        uint32_t bb = bsm_base + (uint32_t)(ky * 1280) + b_off;
        uint32_t B0[4], B1[4];
        ldsm4(B0, bb);
        ldsm4(B1, bb + 32);
        uint32_t arow = asm_base + (uint32_t)((r + ky) * HROWB) + a_off;
#pragma unroll
        for (int t = 0; t < 8; ++t) {
            uint32_t A0[4], A1[4];
            ldsm4(A0, arow + t * 1024);
            ldsm4(A1, arow + t * 1024 + 32);
            mma_f16(acc[t][0], A0, B0[0], B0[1]);
            mma_f16(acc[t][1], A0, B0[2], B0[3]);
            mma_f16(acc[t][0], A1, B1[0], B1[1]);
            mma_f16(acc[t][1], A1, B1[2], B1[3]);
        }
    }

    __syncthreads();
    float* stage = (float*)Asm;
    {
        int q  = lane >> 2;
        int cb = (lane & 3) * 2;
#pragma unroll
        for (int t = 0; t < 8; ++t) {
            int x = t * 16 + q;
#pragma unroll
            for (int h = 0; h < 2; ++h) {
                int co = h * 8 + cb;
                stage[(r * 16 + co)     * 128 + x    ] = acc[t][h][0];
                stage[(r * 16 + co + 1) * 128 + x    ] = acc[t][h][1];
                stage[(r * 16 + co)     * 128 + x + 8] = acc[t][h][2];
                stage[(r * 16 + co + 1) * 128 + x + 8] = acc[t][h][3];
            }
        }
    }
    __syncthreads();
    for (int i = tid; i < 1024; i += 256) {
        int rw = i >> 7, x = i & 127;
        __align__(16) __half h[16];
#pragma unroll
        for (int c = 0; c < 16; ++c)
            h[c] = __float2half_rn(stage[(rw * 16 + c) * 128 + x]);
        uint8_t* dst = xs + (size_t)(img * 128 + y0 + rw) * ROWB + (x + 7) * 48;
        *(uint4*)(dst +  0) = *(const uint4*)&h[0];
        *(uint4*)(dst + 16) = *(const uint4*)&h[8];
        *(uint4*)(dst + 32) = make_uint4(0, 0, 0, 0);
    }
}

// ---------------------------------------------------------------------------
// K3a: sq1 fp16 weights (x1024) into per-(ky,kx) 768B blocks.
// ---------------------------------------------------------------------------
__global__ void split_weights(const float* __restrict__ w, uint8_t* __restrict__ ws) {
    int kxy = blockIdx.x;
    int t   = threadIdx.x;
    int co  = t >> 4, cin = t & 15;
    int ky  = kxy / 15, kx = kxy % 15;
    float wv = w[((size_t)(co * 16 + cin) * 15 + ky) * 15 + kx] * 1024.0f;
    uint8_t* blk = ws + (size_t)kxy * 768;
    *(__half*)(blk + co * 48 + cin * 2) = __float2half_rn(wv);
    if (cin == 0) *(uint4*)(blk + co * 48 + 32) = make_uint4(0, 0, 0, 0);
}

// ---------------------------------------------------------------------------
// K3b: sq2 weights (x1024) per-kx 768B blocks: row n=ky (48B stride), cin*2.
// Row n=15 + pads stay zero (static init).
// ---------------------------------------------------------------------------
__global__ void sq2_ws(const float* __restrict__ w, uint8_t* __restrict__ sw) {
    int kx = blockIdx.x;             // 0..14
    int t  = threadIdx.x;            // 0..255
    int ky = t >> 4, cin = t & 15;
    uint8_t* blk = sw + (size_t)kx * 768;
    if (ky < 15) {
        float wv = w[(size_t)(cin * 15 + ky) * 15 + kx] * 1024.0f;
        *(__half*)(blk + ky * 48 + cin * 2) = __float2half_rn(wv);
    } else if (cin < 3) {            // zero row 15 (3 x 16B)
        *(uint4*)(blk + 15 * 48 + cin * 16) = make_uint4(0, 0, 0, 0);
    }
}

// ---------------------------------------------------------------------------
// K4: sq1 conv 16->16 via fp16 HMMA; epilogue writes fp16 records (g_h1s).
// ---------------------------------------------------------------------------
__global__ __launch_bounds__(256, 1)
void conv_sq1_hmma(const uint8_t* __restrict__ xs, const uint8_t* __restrict__ ws,
                   uint8_t* __restrict__ h1s) {
    extern __shared__ __align__(16) uint8_t sm[];
    uint8_t* Asm = sm;
    uint8_t* Bsm = sm + A_BYTES;

    int tid  = threadIdx.x;
    int lane = tid & 31;
    int w    = tid >> 5;
    int r    = w >> 1;
    int half = w & 1;
    int grp  = blockIdx.x;
    int img  = blockIdx.y;
    int y0   = grp * 4;

    const uint8_t* srcbase = xs + (size_t)img * 128 * ROWB;
    for (int u = tid; u < 18 * 432; u += 256) {
        int slot = u / 432, q = u % 432;
        int yin  = y0 - 7 + slot;
        uint4 v = make_uint4(0, 0, 0, 0);
        if (yin >= 0 && yin < 128)
            v = *(const uint4*)(srcbase + (size_t)yin * ROWB + q * 16);
        *(uint4*)(Asm + slot * ROWB + q * 16) = v;
    }
    for (int u = tid; u < 720; u += 256)
        *(uint4*)(Bsm + u * 16) = *(const uint4*)(ws + u * 16);

    uint32_t asm_base = smem_u32(Asm);
    uint32_t bsm_base = smem_u32(Bsm);
    int part = lane >> 3, rr = lane & 7;
    uint32_t a_off = (uint32_t)((((part & 1) << 3) + rr) * 48 + ((part >> 1) << 4));
    uint32_t b_off = (uint32_t)((((part >> 1) << 3) + rr) * 48 + ((part & 1) << 4));

    float acc[4][2][4];
#pragma unroll
    for (int t = 0; t < 4; ++t)
#pragma unroll
        for (int h = 0; h < 2; ++h)
#pragma unroll
            for (int i = 0; i < 4; ++i) acc[t][h][i] = 0.f;

    __syncthreads();

#pragma unroll 1
    for (int ky = 0; ky < 15; ++ky) {
        if (ky) __syncthreads();
        if (ky < 14) {
            const uint8_t* bw = ws + (size_t)(ky + 1) * B_SLICE;
            uint8_t* bdst = Bsm + ((ky + 1) & 1) * B_SLICE;
            for (int u = tid; u < 720; u += 256)
                *(uint4*)(bdst + u * 16) = *(const uint4*)(bw + u * 16);
        }
        uint32_t bcur = bsm_base + (uint32_t)((ky & 1) * B_SLICE) + b_off;
        uint32_t arow = asm_base + (uint32_t)((r + ky) * ROWB) + a_off
                      + (uint32_t)(half * 4 * 768);

        uint32_t B[2][4], A[2][4][4];
        ldsm4(B[0], bcur);
#pragma unroll
        for (int t = 0; t < 4; ++t) ldsm4(A[0][t], arow + t * 768);

#pragma unroll
        for (int kx = 0; kx < 15; ++kx) {
            int cur = kx & 1, nxt = cur ^ 1;
            if (kx < 14) {
                ldsm4(B[nxt], bcur + (kx + 1) * 768);
                uint32_t an = arow + (kx + 1) * 48;
#pragma unroll
                for (int t = 0; t < 4; ++t) ldsm4(A[nxt][t], an + t * 768);
            }
#pragma unroll
            for (int t = 0; t < 4; ++t) {
                mma_f16(acc[t][0], A[cur][t], B[cur][0], B[cur][1]);
                mma_f16(acc[t][1], A[cur][t], B[cur][2], B[cur][3]);
            }
        }
    }

    __syncthreads();
    float* stage = (float*)Asm;                // [4 rows][16 co][128 x]
    {
        const float sc = 1.0f / 1024.0f;
        int q  = lane >> 2;
        int cb = (lane & 3) * 2;
#pragma unroll
        for (int t = 0; t < 4; ++t) {
            int tt = half * 4 + t;
            int x  = tt * 16 + q;
#pragma unroll
            for (int h = 0; h < 2; ++h) {
                int co = h * 8 + cb;
                stage[(r * 16 + co)     * 128 + x    ] = acc[t][h][0] * sc;
                stage[(r * 16 + co + 1) * 128 + x    ] = acc[t][h][1] * sc;
                stage[(r * 16 + co)     * 128 + x + 8] = acc[t][h][2] * sc;
                stage[(r * 16 + co + 1) * 128 + x + 8] = acc[t][h][3] * sc;
            }
        }
    }
    __syncthreads();
    for (int i = tid; i < 512; i += 256) {     // 4 rows x 128 px fp16 records
        int rw = i >> 7, x = i & 127;
        __align__(16) __half h[16];
#pragma unroll
        for (int c = 0; c < 16; ++c)
            h[c] = __float2half_rn(stage[(rw * 16 + c) * 128 + x]);
        uint8_t* dst = h1s + (size_t)(img * 128 + y0 + rw) * ROWB + (x + 7) * 48;
        *(uint4*)(dst +  0) = *(const uint4*)&h[0];
        *(uint4*)(dst + 16) = *(const uint4*)&h[8];
        *(uint4*)(dst + 32) = make_uint4(0, 0, 0, 0);
    }
}

// ---------------------------------------------------------------------------
// K5a: sq2 GEMM with N=ky. D[yi][ky][x] = sum_{kx,cin} w'[cin][ky][kx]
//      * h1[yi][x+kx-7][cin]. CTA = (img, 8 rows), no vertical halo.
// ---------------------------------------------------------------------------
__global__ __launch_bounds__(256, 2)
void conv_sq2a(const uint8_t* __restrict__ h1s, const uint8_t* __restrict__ sw,
               float* __restrict__ D) {
    extern __shared__ __align__(16) uint8_t sm[];
    uint8_t* Asm = sm;
    uint8_t* Bsm = sm + 8 * ROWB;

    int tid  = threadIdx.x;
    int lane = tid & 31;
    int r    = tid >> 5;             // warp = row 0..7
    int img  = blockIdx.y;
    int y0   = blockIdx.x * 8;

    const uint8_t* src = h1s + (size_t)(img * 128 + y0) * ROWB;
    for (int u = tid; u < 8 * 432; u += 256)
        *(uint4*)(Asm + u * 16) = *(const uint4*)(src + (size_t)u * 16);
    for (int u = tid; u < 720; u += 256)
        *(uint4*)(Bsm + u * 16) = *(const uint4*)(sw + u * 16);

    uint32_t asm_base = smem_u32(Asm);
    uint32_t bsm_base = smem_u32(Bsm);
    int part = lane >> 3, rr = lane & 7;
    uint32_t a_off = (uint32_t)((((part & 1) << 3) + rr) * 48 + ((part >> 1) << 4));
    uint32_t b_off = (uint32_t)((((part >> 1) << 3) + rr) * 48 + ((part & 1) << 4));

    float acc[8][2][4];
#pragma unroll
    for (int t = 0; t < 8; ++t)
#pragma unroll
        for (int h = 0; h < 2; ++h)
#pragma unroll
            for (int i = 0; i < 4; ++i) acc[t][h][i] = 0.f;

    __syncthreads();

    uint32_t arow = asm_base + (uint32_t)(r * ROWB) + a_off;
#pragma unroll 1
    for (int kx = 0; kx < 15; ++kx) {
        uint32_t B[4];
        ldsm4(B, bsm_base + kx * 768 + b_off);
        uint32_t abase = arow + kx * 48;
#pragma unroll
        for (int t = 0; t < 8; ++t) {
            uint32_t A[4];
            ldsm4(A, abase + t * 768);
            mma_f16(acc[t][0], A, B[0], B[1]);
            mma_f16(acc[t][1], A, B[2], B[3]);
        }
    }

    __syncthreads();
    float* stage = (float*)sm;                 // [8 rows][16 ky][128 x] = 64KB
    {
        int q  = lane >> 2;
        int cb = (lane & 3) * 2;
#pragma unroll
        for (int t = 0; t < 8; ++t) {
            int x = t * 16 + q;
#pragma unroll
            for (int h = 0; h < 2; ++h) {
                int n = h * 8 + cb;
                stage[(r * 16 + n)     * 128 + x    ] = acc[t][h][0];
                stage[(r * 16 + n + 1) * 128 + x    ] = acc[t][h][1];
                stage[(r * 16 + n)     * 128 + x + 8] = acc[t][h][2];
                stage[(r * 16 + n + 1) * 128 + x + 8] = acc[t][h][3];
            }
        }
    }
    __syncthreads();
    float4* Dimg = (float4*)(D + (size_t)(img * 128 + y0) * 16 * 128);
    const float4* st4 = (const float4*)stage;
    for (int i = tid; i < 4096; i += 256)      // stage layout == D layout
        Dimg[i] = st4[i];
}

// ---------------------------------------------------------------------------
// K5b: reduce over ky (+unscale) + 2x2 max pool -> heatmaps.
// ---------------------------------------------------------------------------
__global__ __launch_bounds__(256, 8)
void sq2b_reduce_pool(const float* __restrict__ D, float* __restrict__ out) {
    __shared__ float buf[2][128];
    int img = blockIdx.y, yp = blockIdx.x;     // yp 0..63
    int tid = threadIdx.x;
    int r2 = tid >> 7, x = tid & 127;
    int y = yp * 2 + r2;
    float s = 0.f;
#pragma unroll
    for (int ky = 0; ky < 15; ++ky) {
        int yi = y + ky - 7;
        if (yi >= 0 && yi < 128)
            s += D[((size_t)(img * 128 + yi) * 16 + ky) * 128 + x];
    }
    buf[r2][x] = s * (1.0f / 1024.0f);
    __syncthreads();
    if (tid < 64) {
        float m = fmaxf(fmaxf(buf[0][2 * tid], buf[0][2 * tid + 1]),
                        fmaxf(buf[1][2 * tid], buf[1][2 * tid + 1]));
        out[(size_t)img * 4096 + yp * 64 + tid] = m;
    }
}

// ---------------------------------------------------------------------------
// K6: softmax over 64x64 heatmap + soft-argmax. One block per image.
// ---------------------------------------------------------------------------
__global__ void softargmax_kernel(const float* __restrict__ heat,
                                  float* __restrict__ coords) {
    __shared__ float red[256];
    int img = blockIdx.x, tid = threadIdx.x;
    const float* h = heat + (size_t)img * 4096;

    float v[16];
    float m = -1e30f;
#pragma unroll
    for (int i = 0; i < 16; ++i) { v[i] = h[tid + 256 * i]; m = fmaxf(m, v[i]); }

    red[tid] = m; __syncthreads();
    for (int s = 128; s > 0; s >>= 1) {
        if (tid < s) red[tid] = fmaxf(red[tid], red[tid + s]);
        __syncthreads();
    }
    m = red[0]; __syncthreads();

    float se = 0.f, sx = 0.f, sy = 0.f;
#pragma unroll
    for (int i = 0; i < 16; ++i) {
        int k = tid + 256 * i;
        float e = expf(v[i] - m);
        se += e;
        sx += e * (float)(k & 63);
        sy += e * (float)(k >> 6);
    }

    red[tid] = se; __syncthreads();
    for (int s = 128; s > 0; s >>= 1) { if (tid < s) red[tid] += red[tid + s]; __syncthreads(); }
    float tot = red[0]; __syncthreads();

    red[tid] = sx; __syncthreads();
    for (int s = 128; s > 0; s >>= 1) { if (tid < s) red[tid] += red[tid + s]; __syncthreads(); }
    float totx = red[0]; __syncthreads();

    red[tid] = sy; __syncthreads();
    for (int s = 128; s > 0; s >>= 1) { if (tid < s) red[tid] += red[tid + s]; __syncthreads(); }
    float toty = red[0];

    if (tid == 0) {
        coords[img * 2 + 0] = totx / (63.0f * tot);
        coords[img * 2 + 1] = toty / (63.0f * tot);
    }
}

// ---------------------------------------------------------------------------
extern "C" void kernel_launch(void* const* d_in, const int* in_sizes, int n_in,
                              void* d_out, int out_size) {
    const float* x      = (const float*)d_in[0];
    const float* head_w = (const float*)d_in[1];
    const float* sq1_w  = (const float*)d_in[2];
    const float* sq2_w  = (const float*)d_in[3];
    const float* mtc    = (const float*)d_in[4];
    float* out = (float*)d_out;

    float *zp, *dp;
    uint8_t *xsp, *h1sp, *hzp, *wsp, *hwp, *swp;
    cudaGetSymbolAddress((void**)&zp,   g_z);
    cudaGetSymbolAddress((void**)&dp,   g_d);
    cudaGetSymbolAddress((void**)&xsp,  g_xs);
    cudaGetSymbolAddress((void**)&h1sp, g_h1s);
    cudaGetSymbolAddress((void**)&hzp,  g_hz);
    cudaGetSymbolAddress((void**)&wsp,  g_ws);
    cudaGetSymbolAddress((void**)&hwp,  g_hw);
    cudaGetSymbolAddress((void**)&swp,  g_sw);

    cudaFuncSetAttribute(conv_sq1_hmma,
                         cudaFuncAttributeMaxDynamicSharedMemorySize, SQ1_SMEM);
    cudaFuncSetAttribute(conv_head_hmma,
                         cudaFuncAttributeMaxDynamicSharedMemorySize, H_SMEM);
    cudaFuncSetAttribute(conv_sq2a,
                         cudaFuncAttributeMaxDynamicSharedMemorySize, SQ2A_SMEM);

    integrate_kernel<<<512, 256>>>(x, mtc, zp);
    split_weights<<<225, 256>>>(sq1_w, wsp);
    head_ws<<<15, 512>>>(head_w, hwp);
    sq2_ws<<<15, 256>>>(sq2_w, swp);
    head_recs<<<dim3(128, NIMG), 128>>>(zp, hzp);
    conv_head_hmma<<<dim3(16, NIMG), 256, H_SMEM>>>(hzp, hwp, xsp);
    conv_sq1_hmma<<<dim3(32, NIMG), 256, SQ1_SMEM>>>(xsp, wsp, h1sp);
    conv_sq2a<<<dim3(16, NIMG), 256, SQ2A_SMEM>>>(h1sp, swp, dp);
    sq2b_reduce_pool<<<dim3(64, NIMG), 256>>>(dp, out);

    if (out_size >= NIMG * 4096 + NIMG * 2) {
        softargmax_kernel<<<NIMG, 256>>>(out, out + (size_t)NIMG * 4096);
    }
}

// round 13
// speedup vs baseline: 1.3658x; 1.0046x over previous
#include <cuda_runtime.h>
#include <cuda_bf16.h>
#include <cuda_fp16.h>
#include <math.h>
#include <stdint.h>

#define NIMG 64          // T*B = 16*4
#define HW   16384       // 128*128
typedef unsigned long long ull;

// Scratch (allocation-free rule: __device__ globals; zero-init at load)
__device__ float   g_z [NIMG *  2 * HW];                 //  8 MB integrated input
__device__ uint8_t g_xs [(size_t)NIMG * 128 * 144 * 48]; // 56.6 MB fp16 recs (sq1 A)
__device__ uint8_t g_h1s[(size_t)NIMG * 128 * 144 * 48]; // 56.6 MB fp16 recs (sq2 A)
__device__ uint8_t g_hz[(size_t)NIMG * 128 * 128 * 64];  // 67 MB head A records
__device__ float   g_d [(size_t)NIMG * 128 * 16 * 128];  // 67 MB sq2 D[yi][ky][x]
__device__ uint8_t g_ws[225 * 768];                      // sq1 fp16 weights (x1024)
__device__ uint8_t g_hw[15 * 1280];                      // head fp16 weights per-ky
__device__ uint8_t g_sw[15 * 768];                       // sq2 fp16 weights per-kx (x1024)

#define ROWB 6912                        // 144 px * 48 B
#define A_BYTES (18 * ROWB)              // 124416
#define B_SLICE 11520                    // 15 kx * 768
#define SQ1_SMEM (A_BYTES + 2 * B_SLICE) // 147456

#define HROWB 8192                       // head: 128 recs * 64 B
#define H_A_BYTES (22 * HROWB)           // 180224
#define H_SMEM (H_A_BYTES + 15 * 1280)   // 199424

#define SQ2A_SMEM 66816                  // max(8*ROWB + 15*768, 64KB stage)

// ---- HMMA helpers ---------------------------------------------------------
__device__ __forceinline__ uint32_t smem_u32(const void* p) {
    uint32_t a;
    asm("{ .reg .u64 t; cvta.to.shared.u64 t, %1; cvt.u32.u64 %0, t; }" : "=r"(a) : "l"(p));
    return a;
}
__device__ __forceinline__ void ldsm4(uint32_t* r, uint32_t a) {
    asm volatile("ldmatrix.sync.aligned.m8n8.x4.shared.b16 {%0,%1,%2,%3}, [%4];"
                 : "=r"(r[0]), "=r"(r[1]), "=r"(r[2]), "=r"(r[3]) : "r"(a));
}
__device__ __forceinline__ void mma_f16(float* d, const uint32_t* a,
                                        uint32_t b0, uint32_t b1) {
    asm volatile(
        "mma.sync.aligned.m16n8k16.row.col.f32.f16.f16.f32 "
        "{%0,%1,%2,%3}, {%4,%5,%6,%7}, {%8,%9}, {%0,%1,%2,%3};"
        : "+f"(d[0]), "+f"(d[1]), "+f"(d[2]), "+f"(d[3])
        : "r"(a[0]), "r"(a[1]), "r"(a[2]), "r"(a[3]), "r"(b0), "r"(b1));
}

// ---------------------------------------------------------------------------
// K1: leaky integration over T per TC slice + mean over TC.
// ---------------------------------------------------------------------------
__global__ void integrate_kernel(const float* __restrict__ x,
                                 const float* __restrict__ mtc_p,
                                 float* __restrict__ z) {
    int idx = blockIdx.x * blockDim.x + threadIdx.x;
    if (idx >= 4 * 2 * HW) return;
    int p  = idx & (HW - 1);
    int bc = idx >> 14;
    int c  = bc & 1;
    int b  = bc >> 1;

    float mtc = *mtc_p;
    float al[5], om[5];
#pragma unroll
    for (int tc = 0; tc < 5; ++tc) {
        float tau = mtc * exp2f(0.5f * (float)(tc - 2));
        al[tc] = expf(-1.0f / tau);
        om[tc] = 1.0f - al[tc];
    }
    float s[5] = {0.f, 0.f, 0.f, 0.f, 0.f};
    for (int t = 0; t < 16; ++t) {
        float acc = 0.f;
#pragma unroll
        for (int tc = 0; tc < 5; ++tc) {
            float v = x[(size_t)((t * 4 + b) * 10 + tc * 2 + c) * HW + p];
            s[tc] = al[tc] * s[tc] + om[tc] * v;
            acc += s[tc];
        }
        z[(size_t)((t * 4 + b) * 2 + c) * HW + p] = acc * 0.2f;
    }
}

// ---------------------------------------------------------------------------
// K2a: head A-record prepass. Per (img,y): 128 records of 64B.
// ---------------------------------------------------------------------------
__global__ __launch_bounds__(128, 8)
void head_recs(const float* __restrict__ z, uint8_t* __restrict__ hz) {
    __shared__ float zrow[2][128];
    int y = blockIdx.x, img = blockIdx.y;
    int x = threadIdx.x;
    zrow[0][x] = z[((size_t)(img * 2 + 0) * 128 + y) * 128 + x];
    zrow[1][x] = z[((size_t)(img * 2 + 1) * 128 + y) * 128 + x];
    __syncthreads();

    __align__(16) __half h[32];
#pragma unroll
    for (int kx = 0; kx < 16; ++kx) {
        int xi = x + kx - 7;
        bool v = (kx < 15) && (xi >= 0) && (xi < 128);
        h[kx * 2 + 0] = v ? __float2half_rn(zrow[0][xi]) : __half(0.f);
        h[kx * 2 + 1] = v ? __float2half_rn(zrow[1][xi]) : __half(0.f);
    }
    uint8_t* dst = hz + ((size_t)(img * 128 + y) * 128 + x) * 64;
    *(uint4*)(dst +  0) = *(const uint4*)&h[0];
    *(uint4*)(dst + 16) = *(const uint4*)&h[8];
    *(uint4*)(dst + 32) = *(const uint4*)&h[16];
    *(uint4*)(dst + 48) = *(const uint4*)&h[24];
}

// ---------------------------------------------------------------------------
// K2b: head weight prepass (per ky 1280B block, 80B co rows).
// ---------------------------------------------------------------------------
__global__ void head_ws(const float* __restrict__ w, uint8_t* __restrict__ hw) {
    int ky = blockIdx.x;
    int t  = threadIdx.x;            // 0..511
    int co = t >> 5, k = t & 31;
    int kx = k >> 1, c = k & 1;
    float wv = (kx < 15) ? w[((size_t)(co * 2 + c) * 15 + ky) * 15 + kx] : 0.f;
    uint8_t* blk = hw + (size_t)ky * 1280;
    *(__half*)(blk + co * 80 + k * 2) = __float2half_rn(wv);
    if (k == 0) *(uint4*)(blk + co * 80 + 64) = make_uint4(0, 0, 0, 0);
}

// ---------------------------------------------------------------------------
// K2c: head conv 2->16 via fp16 HMMA. Writes g_xs fp16 records.
// ---------------------------------------------------------------------------
__global__ __launch_bounds__(256, 1)
void conv_head_hmma(const uint8_t* __restrict__ hz, const uint8_t* __restrict__ hw,
                    uint8_t* __restrict__ xs) {
    extern __shared__ __align__(16) uint8_t sm[];
    uint8_t* Asm = sm;
    uint8_t* Bsm = sm + H_A_BYTES;

    int tid  = threadIdx.x;
    int lane = tid & 31;
    int r    = tid >> 5;
    int grp  = blockIdx.x;
    int img  = blockIdx.y;
    int y0   = grp * 8;

    const uint8_t* srcbase = hz + (size_t)img * 128 * HROWB;
    for (int u = tid; u < 22 * 512; u += 256) {
        int slot = u >> 9, q = u & 511;
        int yin  = y0 - 7 + slot;
        uint4 v = make_uint4(0, 0, 0, 0);
        if (yin >= 0 && yin < 128)
            v = *(const uint4*)(srcbase + (size_t)yin * HROWB + q * 16);
        *(uint4*)(Asm + slot * HROWB + q * 16) = v;
    }
    for (int u = tid; u < 1200; u += 256)
        *(uint4*)(Bsm + u * 16) = *(const uint4*)(hw + u * 16);

    uint32_t asm_base = smem_u32(Asm);
    uint32_t bsm_base = smem_u32(Bsm);
    int part = lane >> 3, rr = lane & 7;
    uint32_t a_off = (uint32_t)((((part & 1) << 3) + rr) * 64 + ((part >> 1) << 4));
    uint32_t b_off = (uint32_t)((((part >> 1) << 3) + rr) * 80 + ((part & 1) << 4));

    float acc[8][2][4];
#pragma unroll
    for (int t = 0; t < 8; ++t)
#pragma unroll
        for (int h = 0; h < 2; ++h)
#pragma unroll
            for (int i = 0; i < 4; ++i) acc[t][h][i] = 0.f;

    __syncthreads();

#pragma unroll 1
    for (int ky = 0; ky < 15; ++ky) {
        uint32_t bb = bsm_base + (uint32_t)(ky * 1280) + b_off;
        uint32_t B0[4], B1[4];
        ldsm4(B0, bb);
        ldsm4(B1, bb + 32);
        uint32_t arow = asm_base + (uint32_t)((r + ky) * HROWB) + a_off;
#pragma unroll
        for (int t = 0; t < 8; ++t) {
            uint32_t A0[4], A1[4];
            ldsm4(A0, arow + t * 1024);
            ldsm4(A1, arow + t * 1024 + 32);
            mma_f16(acc[t][0], A0, B0[0], B0[1]);
            mma_f16(acc[t][1], A0, B0[2], B0[3]);
            mma_f16(acc[t][0], A1, B1[0], B1[1]);
            mma_f16(acc[t][1], A1, B1[2], B1[3]);
        }
    }

    __syncthreads();
    float* stage = (float*)Asm;
    {
        int q  = lane >> 2;
        int cb = (lane & 3) * 2;
#pragma unroll
        for (int t = 0; t < 8; ++t) {
            int x = t * 16 + q;
#pragma unroll
            for (int h = 0; h < 2; ++h) {
                int co = h * 8 + cb;
                stage[(r * 16 + co)     * 128 + x    ] = acc[t][h][0];
                stage[(r * 16 + co + 1) * 128 + x    ] = acc[t][h][1];
                stage[(r * 16 + co)     * 128 + x + 8] = acc[t][h][2];
                stage[(r * 16 + co + 1) * 128 + x + 8] = acc[t][h][3];
            }
        }
    }
    __syncthreads();
    for (int i = tid; i < 1024; i += 256) {
        int rw = i >> 7, x = i & 127;
        __align__(16) __half h[16];
#pragma unroll
        for (int c = 0; c < 16; ++c)
            h[c] = __float2half_rn(stage[(rw * 16 + c) * 128 + x]);
        uint8_t* dst = xs + (size_t)(img * 128 + y0 + rw) * ROWB + (x + 7) * 48;
        *(uint4*)(dst +  0) = *(const uint4*)&h[0];
        *(uint4*)(dst + 16) = *(const uint4*)&h[8];
        *(uint4*)(dst + 32) = make_uint4(0, 0, 0, 0);
    }
}

// ---------------------------------------------------------------------------
// K3a: sq1 fp16 weights (x1024) into per-(ky,kx) 768B blocks.
// ---------------------------------------------------------------------------
__global__ void split_weights(const float* __restrict__ w, uint8_t* __restrict__ ws) {
    int kxy = blockIdx.x;
    int t   = threadIdx.x;
    int co  = t >> 4, cin = t & 15;
    int ky  = kxy / 15, kx = kxy % 15;
    float wv = w[((size_t)(co * 16 + cin) * 15 + ky) * 15 + kx] * 1024.0f;
    uint8_t* blk = ws + (size_t)kxy * 768;
    *(__half*)(blk + co * 48 + cin * 2) = __float2half_rn(wv);
    if (cin == 0) *(uint4*)(blk + co * 48 + 32) = make_uint4(0, 0, 0, 0);
}

// ---------------------------------------------------------------------------
// K3b: sq2 weights (x1024) per-kx 768B blocks: row n=ky (48B stride), cin*2.
// Row n=15 + pads stay zero (static init).
// ---------------------------------------------------------------------------
__global__ void sq2_ws(const float* __restrict__ w, uint8_t* __restrict__ sw) {
    int kx = blockIdx.x;             // 0..14
    int t  = threadIdx.x;            // 0..255
    int ky = t >> 4, cin = t & 15;
    uint8_t* blk = sw + (size_t)kx * 768;
    if (ky < 15) {
        float wv = w[(size_t)(cin * 15 + ky) * 15 + kx] * 1024.0f;
        *(__half*)(blk + ky * 48 + cin * 2) = __float2half_rn(wv);
    } else if (cin < 3) {            // zero row 15 (3 x 16B)
        *(uint4*)(blk + 15 * 48 + cin * 16) = make_uint4(0, 0, 0, 0);
    }
}

// ---------------------------------------------------------------------------
// K4: sq1 conv 16->16 via fp16 HMMA; epilogue writes fp16 records (g_h1s).
// ---------------------------------------------------------------------------
__global__ __launch_bounds__(256, 1)
void conv_sq1_hmma(const uint8_t* __restrict__ xs, const uint8_t* __restrict__ ws,
                   uint8_t* __restrict__ h1s) {
    extern __shared__ __align__(16) uint8_t sm[];
    uint8_t* Asm = sm;
    uint8_t* Bsm = sm + A_BYTES;

    int tid  = threadIdx.x;
    int lane = tid & 31;
    int w    = tid >> 5;
    int r    = w >> 1;
    int half = w & 1;
    int grp  = blockIdx.x;
    int img  = blockIdx.y;
    int y0   = grp * 4;

    const uint8_t* srcbase = xs + (size_t)img * 128 * ROWB;
    for (int u = tid; u < 18 * 432; u += 256) {
        int slot = u / 432, q = u % 432;
        int yin  = y0 - 7 + slot;
        uint4 v = make_uint4(0, 0, 0, 0);
        if (yin >= 0 && yin < 128)
            v = *(const uint4*)(srcbase + (size_t)yin * ROWB + q * 16);
        *(uint4*)(Asm + slot * ROWB + q * 16) = v;
    }
    for (int u = tid; u < 720; u += 256)
        *(uint4*)(Bsm + u * 16) = *(const uint4*)(ws + u * 16);

    uint32_t asm_base = smem_u32(Asm);
    uint32_t bsm_base = smem_u32(Bsm);
    int part = lane >> 3, rr = lane & 7;
    uint32_t a_off = (uint32_t)((((part & 1) << 3) + rr) * 48 + ((part >> 1) << 4));
    uint32_t b_off = (uint32_t)((((part >> 1) << 3) + rr) * 48 + ((part & 1) << 4));

    float acc[4][2][4];
#pragma unroll
    for (int t = 0; t < 4; ++t)
#pragma unroll
        for (int h = 0; h < 2; ++h)
#pragma unroll
            for (int i = 0; i < 4; ++i) acc[t][h][i] = 0.f;

    __syncthreads();

#pragma unroll 1
    for (int ky = 0; ky < 15; ++ky) {
        if (ky) __syncthreads();
        if (ky < 14) {
            const uint8_t* bw = ws + (size_t)(ky + 1) * B_SLICE;
            uint8_t* bdst = Bsm + ((ky + 1) & 1) * B_SLICE;
            for (int u = tid; u < 720; u += 256)
                *(uint4*)(bdst + u * 16) = *(const uint4*)(bw + u * 16);
        }
        uint32_t bcur = bsm_base + (uint32_t)((ky & 1) * B_SLICE) + b_off;
        uint32_t arow = asm_base + (uint32_t)((r + ky) * ROWB) + a_off
                      + (uint32_t)(half * 4 * 768);

        uint32_t B[2][4], A[2][4][4];
        ldsm4(B[0], bcur);
#pragma unroll
        for (int t = 0; t < 4; ++t) ldsm4(A[0][t], arow + t * 768);

#pragma unroll
        for (int kx = 0; kx < 15; ++kx) {
            int cur = kx & 1, nxt = cur ^ 1;
            if (kx < 14) {
                ldsm4(B[nxt], bcur + (kx + 1) * 768);
                uint32_t an = arow + (kx + 1) * 48;
#pragma unroll
                for (int t = 0; t < 4; ++t) ldsm4(A[nxt][t], an + t * 768);
            }
#pragma unroll
            for (int t = 0; t < 4; ++t) {
                mma_f16(acc[t][0], A[cur][t], B[cur][0], B[cur][1]);
                mma_f16(acc[t][1], A[cur][t], B[cur][2], B[cur][3]);
            }
        }
    }

    __syncthreads();
    float* stage = (float*)Asm;                // [4 rows][16 co][128 x]
    {
        const float sc = 1.0f / 1024.0f;
        int q  = lane >> 2;
        int cb = (lane & 3) * 2;
#pragma unroll
        for (int t = 0; t < 4; ++t) {
            int tt = half * 4 + t;
            int x  = tt * 16 + q;
#pragma unroll
            for (int h = 0; h < 2; ++h) {
                int co = h * 8 + cb;
                stage[(r * 16 + co)     * 128 + x    ] = acc[t][h][0] * sc;
                stage[(r * 16 + co + 1) * 128 + x    ] = acc[t][h][1] * sc;
                stage[(r * 16 + co)     * 128 + x + 8] = acc[t][h][2] * sc;
                stage[(r * 16 + co + 1) * 128 + x + 8] = acc[t][h][3] * sc;
            }
        }
    }
    __syncthreads();
    for (int i = tid; i < 512; i += 256) {     // 4 rows x 128 px fp16 records
        int rw = i >> 7, x = i & 127;
        __align__(16) __half h[16];
#pragma unroll
        for (int c = 0; c < 16; ++c)
            h[c] = __float2half_rn(stage[(rw * 16 + c) * 128 + x]);
        uint8_t* dst = h1s + (size_t)(img * 128 + y0 + rw) * ROWB + (x + 7) * 48;
        *(uint4*)(dst +  0) = *(const uint4*)&h[0];
        *(uint4*)(dst + 16) = *(const uint4*)&h[8];
        *(uint4*)(dst + 32) = make_uint4(0, 0, 0, 0);
    }
}

// ---------------------------------------------------------------------------
// K5a: sq2 GEMM with N=ky. D[yi][ky][x] = sum_{kx,cin} w'[cin][ky][kx]
//      * h1[yi][x+kx-7][cin]. CTA = (img, 8 rows), no vertical halo.
// ---------------------------------------------------------------------------
__global__ __launch_bounds__(256, 2)
void conv_sq2a(const uint8_t* __restrict__ h1s, const uint8_t* __restrict__ sw,
               float* __restrict__ D) {
    extern __shared__ __align__(16) uint8_t sm[];
    uint8_t* Asm = sm;
    uint8_t* Bsm = sm + 8 * ROWB;

    int tid  = threadIdx.x;
    int lane = tid & 31;
    int r    = tid >> 5;             // warp = row 0..7
    int img  = blockIdx.y;
    int y0   = blockIdx.x * 8;

    const uint8_t* src = h1s + (size_t)(img * 128 + y0) * ROWB;
    for (int u = tid; u < 8 * 432; u += 256)
        *(uint4*)(Asm + u * 16) = *(const uint4*)(src + (size_t)u * 16);
    for (int u = tid; u < 720; u += 256)
        *(uint4*)(Bsm + u * 16) = *(const uint4*)(sw + u * 16);

    uint32_t asm_base = smem_u32(Asm);
    uint32_t bsm_base = smem_u32(Bsm);
    int part = lane >> 3, rr = lane & 7;
    uint32_t a_off = (uint32_t)((((part & 1) << 3) + rr) * 48 + ((part >> 1) << 4));
    uint32_t b_off = (uint32_t)((((part >> 1) << 3) + rr) * 48 + ((part & 1) << 4));

    float acc[8][2][4];
#pragma unroll
    for (int t = 0; t < 8; ++t)
#pragma unroll
        for (int h = 0; h < 2; ++h)
#pragma unroll
            for (int i = 0; i < 4; ++i) acc[t][h][i] = 0.f;

    __syncthreads();

    uint32_t arow = asm_base + (uint32_t)(r * ROWB) + a_off;
#pragma unroll 1
    for (int kx = 0; kx < 15; ++kx) {
        uint32_t B[4];
        ldsm4(B, bsm_base + kx * 768 + b_off);
        uint32_t abase = arow + kx * 48;
#pragma unroll
        for (int t = 0; t < 8; ++t) {
            uint32_t A[4];
            ldsm4(A, abase + t * 768);
            mma_f16(acc[t][0], A, B[0], B[1]);
            mma_f16(acc[t][1], A, B[2], B[3]);
        }
    }

    __syncthreads();
    float* stage = (float*)sm;                 // [8 rows][16 ky][128 x] = 64KB
    {
        int q  = lane >> 2;
        int cb = (lane & 3) * 2;
#pragma unroll
        for (int t = 0; t < 8; ++t) {
            int x = t * 16 + q;
#pragma unroll
            for (int h = 0; h < 2; ++h) {
                int n = h * 8 + cb;
                stage[(r * 16 + n)     * 128 + x    ] = acc[t][h][0];
                stage[(r * 16 + n + 1) * 128 + x    ] = acc[t][h][1];
                stage[(r * 16 + n)     * 128 + x + 8] = acc[t][h][2];
                stage[(r * 16 + n + 1) * 128 + x + 8] = acc[t][h][3];
            }
        }
    }
    __syncthreads();
    float4* Dimg = (float4*)(D + (size_t)(img * 128 + y0) * 16 * 128);
    const float4* st4 = (const float4*)stage;
    for (int i = tid; i < 4096; i += 256)      // stage layout == D layout
        Dimg[i] = st4[i];
}

// ---------------------------------------------------------------------------
// K5b: reduce over ky (+unscale) + 2x2 max pool -> heatmaps.
// ---------------------------------------------------------------------------
__global__ __launch_bounds__(256, 8)
void sq2b_reduce_pool(const float* __restrict__ D, float* __restrict__ out) {
    __shared__ float buf[2][128];
    int img = blockIdx.y, yp = blockIdx.x;     // yp 0..63
    int tid = threadIdx.x;
    int r2 = tid >> 7, x = tid & 127;
    int y = yp * 2 + r2;
    float s = 0.f;
#pragma unroll
    for (int ky = 0; ky < 15; ++ky) {
        int yi = y + ky - 7;
        if (yi >= 0 && yi < 128)
            s += D[((size_t)(img * 128 + yi) * 16 + ky) * 128 + x];
    }
    buf[r2][x] = s * (1.0f / 1024.0f);
    __syncthreads();
    if (tid < 64) {
        float m = fmaxf(fmaxf(buf[0][2 * tid], buf[0][2 * tid + 1]),
                        fmaxf(buf[1][2 * tid], buf[1][2 * tid + 1]));
        out[(size_t)img * 4096 + yp * 64 + tid] = m;
    }
}

// ---------------------------------------------------------------------------
// K6: softmax over 64x64 heatmap + soft-argmax. One block per image.
// ---------------------------------------------------------------------------
__global__ void softargmax_kernel(const float* __restrict__ heat,
                                  float* __restrict__ coords) {
    __shared__ float red[256];
    int img = blockIdx.x, tid = threadIdx.x;
    const float* h = heat + (size_t)img * 4096;

    float v[16];
    float m = -1e30f;
#pragma unroll
    for (int i = 0; i < 16; ++i) { v[i] = h[tid + 256 * i]; m = fmaxf(m, v[i]); }

    red[tid] = m; __syncthreads();
    for (int s = 128; s > 0; s >>= 1) {
        if (tid < s) red[tid] = fmaxf(red[tid], red[tid + s]);
        __syncthreads();
    }
    m = red[0]; __syncthreads();

    float se = 0.f, sx = 0.f, sy = 0.f;
#pragma unroll
    for (int i = 0; i < 16; ++i) {
        int k = tid + 256 * i;
        float e = expf(v[i] - m);
        se += e;
        sx += e * (float)(k & 63);
        sy += e * (float)(k >> 6);
    }

    red[tid] = se; __syncthreads();
    for (int s = 128; s > 0; s >>= 1) { if (tid < s) red[tid] += red[tid + s]; __syncthreads(); }
    float tot = red[0]; __syncthreads();

    red[tid] = sx; __syncthreads();
    for (int s = 128; s > 0; s >>= 1) { if (tid < s) red[tid] += red[tid + s]; __syncthreads(); }
    float totx = red[0]; __syncthreads();

    red[tid] = sy; __syncthreads();
    for (int s = 128; s > 0; s >>= 1) { if (tid < s) red[tid] += red[tid + s]; __syncthreads(); }
    float toty = red[0];

    if (tid == 0) {
        coords[img * 2 + 0] = totx / (63.0f * tot);
        coords[img * 2 + 1] = toty / (63.0f * tot);
    }
}

// ---------------------------------------------------------------------------
extern "C" void kernel_launch(void* const* d_in, const int* in_sizes, int n_in,
                              void* d_out, int out_size) {
    const float* x      = (const float*)d_in[0];
    const float* head_w = (const float*)d_in[1];
    const float* sq1_w  = (const float*)d_in[2];
    const float* sq2_w  = (const float*)d_in[3];
    const float* mtc    = (const float*)d_in[4];
    float* out = (float*)d_out;

    float *zp, *dp;
    uint8_t *xsp, *h1sp, *hzp, *wsp, *hwp, *swp;
    cudaGetSymbolAddress((void**)&zp,   g_z);
    cudaGetSymbolAddress((void**)&dp,   g_d);
    cudaGetSymbolAddress((void**)&xsp,  g_xs);
    cudaGetSymbolAddress((void**)&h1sp, g_h1s);
    cudaGetSymbolAddress((void**)&hzp,  g_hz);
    cudaGetSymbolAddress((void**)&wsp,  g_ws);
    cudaGetSymbolAddress((void**)&hwp,  g_hw);
    cudaGetSymbolAddress((void**)&swp,  g_sw);

    cudaFuncSetAttribute(conv_sq1_hmma,
                         cudaFuncAttributeMaxDynamicSharedMemorySize, SQ1_SMEM);
    cudaFuncSetAttribute(conv_head_hmma,
                         cudaFuncAttributeMaxDynamicSharedMemorySize, H_SMEM);
    cudaFuncSetAttribute(conv_sq2a,
                         cudaFuncAttributeMaxDynamicSharedMemorySize, SQ2A_SMEM);

    integrate_kernel<<<512, 256>>>(x, mtc, zp);
    split_weights<<<225, 256>>>(sq1_w, wsp);
    head_ws<<<15, 512>>>(head_w, hwp);
    sq2_ws<<<15, 256>>>(sq2_w, swp);
    head_recs<<<dim3(128, NIMG), 128>>>(zp, hzp);
    conv_head_hmma<<<dim3(16, NIMG), 256, H_SMEM>>>(hzp, hwp, xsp);
    conv_sq1_hmma<<<dim3(32, NIMG), 256, SQ1_SMEM>>>(xsp, wsp, h1sp);
    conv_sq2a<<<dim3(16, NIMG), 256, SQ2A_SMEM>>>(h1sp, swp, dp);
    sq2b_reduce_pool<<<dim3(64, NIMG), 256>>>(dp, out);

    if (out_size >= NIMG * 4096 + NIMG * 2) {
        softargmax_kernel<<<NIMG, 256>>>(out, out + (size_t)NIMG * 4096);
    }
}